// round 13
// baseline (speedup 1.0000x reference)
#include <cuda_runtime.h>
#include <cuda_bf16.h>
#include <cstdint>
#include <cstddef>

typedef __nv_bfloat16 bf16;

// ---------------- problem constants ----------------
#define NTOK     32768
#define DD       256
#define QKVC     2560

// ---------------- static scratch ----------------
__device__ int8_t g_aq8 [(size_t)NTOK * 512];    // LN1 out int8: [row][i1:256|i2:256]
__device__ float  g_asc [NTOK];                  // per-row scale (s/127)
__device__ int8_t g_wq8 [(size_t)QKVC * 512];    // qkv weights int8: [j][i1|i2] over d
__device__ float  g_wsc [QKVC];                  // per-col scale (s/127)
__device__ bf16 g_w1sp [(size_t)DD * 512];
__device__ bf16 g_w2sp [(size_t)DD * 512];
__device__ bf16 g_ln2sp[(size_t)NTOK * 512];
__device__ bf16 g_qkvsp[(size_t)NTOK * 5120];
__device__ float g_z1  [(size_t)NTOK * DD];
__device__ float g_z2  [(size_t)NTOK * DD];
__device__ float g_so  [2048];
__device__ float g_x2  [(size_t)NTOK * DD];

// ---------------- helpers ----------------
__device__ __forceinline__ void bsplit(float v, bf16& h, bf16& l) {
    h = __float2bfloat16_rn(v);
    l = __float2bfloat16_rn(v - __bfloat162float(h));
}
__device__ __forceinline__ void cpasync16(uint32_t s, const void* g) {
    asm volatile("cp.async.cg.shared.global [%0], [%1], 16;\n" :: "r"(s), "l"(g));
}
__device__ __forceinline__ void mma16816(float* c, const uint32_t* a, const uint32_t* b) {
    asm volatile(
        "mma.sync.aligned.m16n8k16.row.col.f32.bf16.bf16.f32 "
        "{%0,%1,%2,%3},{%4,%5,%6,%7},{%8,%9},{%0,%1,%2,%3};\n"
        : "+f"(c[0]), "+f"(c[1]), "+f"(c[2]), "+f"(c[3])
        : "r"(a[0]), "r"(a[1]), "r"(a[2]), "r"(a[3]), "r"(b[0]), "r"(b[1]));
}
__device__ __forceinline__ void mma_s8(int* c, const uint32_t* a, const uint32_t* b) {
    asm volatile(
        "mma.sync.aligned.m16n8k32.row.col.s32.s8.s8.s32 "
        "{%0,%1,%2,%3},{%4,%5,%6,%7},{%8,%9},{%0,%1,%2,%3};\n"
        : "+r"(c[0]), "+r"(c[1]), "+r"(c[2]), "+r"(c[3])
        : "r"(a[0]), "r"(a[1]), "r"(a[2]), "r"(a[3]), "r"(b[0]), "r"(b[1]));
}
__device__ __forceinline__ void ldsm_x4(uint32_t* r, uint32_t a) {
    asm volatile("ldmatrix.sync.aligned.m8n8.x4.shared.b16 {%0,%1,%2,%3}, [%4];"
        : "=r"(r[0]), "=r"(r[1]), "=r"(r[2]), "=r"(r[3]) : "r"(a));
}
__device__ __forceinline__ void ldsm_x2(uint32_t* r, uint32_t a) {
    asm volatile("ldmatrix.sync.aligned.m8n8.x2.shared.b16 {%0,%1}, [%2];"
        : "=r"(r[0]), "=r"(r[1]) : "r"(a));
}
__device__ __forceinline__ void ldsm_x2t(uint32_t* r, uint32_t a) {
    asm volatile("ldmatrix.sync.aligned.m8n8.x2.trans.shared.b16 {%0,%1}, [%2];"
        : "=r"(r[0]), "=r"(r[1]) : "r"(a));
}
// 2-level int8 quantize: y in [-127,127]; i1 + i2/254 ~= y
__device__ __forceinline__ void q2(float y, int& i1, int& i2) {
    i1 = __float2int_rn(y);
    i2 = __float2int_rn((y - (float)i1) * 254.0f);
}

// ---------------- weight prep: int8 2-level, per-column scale ----------------
// one warp per output column j (W[d][j], d = 0..255)
__global__ void prep_wqkv_q8(const float* __restrict__ q,
                             const float* __restrict__ k,
                             const float* __restrict__ v) {
    int j    = (blockIdx.x * blockDim.x + threadIdx.x) >> 5;   // 0..2559
    int lane = threadIdx.x & 31;
    float vals[8];
    float amax = 0.f;
#pragma unroll
    for (int t = 0; t < 8; t++) {
        int d = lane * 8 + t;
        float val;
        if (j < 2048) { int h = j >> 8, kk = j & 255; val = q[((size_t)(h * 256 + d)) * 256 + kk]; }
        else if (j < 2304) val = k[(size_t)d * 256 + (j - 2048)];
        else               val = v[(size_t)d * 256 + (j - 2304)];
        vals[t] = val;
        amax = fmaxf(amax, fabsf(val));
    }
#pragma unroll
    for (int o = 16; o > 0; o >>= 1) amax = fmaxf(amax, __shfl_xor_sync(0xffffffffu, amax, o));
    amax = fmaxf(amax, 1e-20f);
    float inv = 127.0f / amax;
    if (lane == 0) g_wsc[j] = amax * (1.0f / 127.0f);
    uint32_t p1 = 0, p2 = 0;
    int8_t* base = g_wq8 + (size_t)j * 512;
#pragma unroll
    for (int t = 0; t < 8; t++) {
        int i1, i2; q2(vals[t] * inv, i1, i2);
        int b = t & 3;
        p1 |= (uint32_t)(uint8_t)(int8_t)i1 << (b * 8);
        p2 |= (uint32_t)(uint8_t)(int8_t)i2 << (b * 8);
        if (b == 3) {
            *(uint32_t*)(base + lane * 8 + (t - 3))       = p1;
            *(uint32_t*)(base + 256 + lane * 8 + (t - 3)) = p2;
            p1 = 0; p2 = 0;
        }
    }
}

__global__ void prep_wt_kernel(const float* __restrict__ src, bf16* __restrict__ dst) {
    int idx = blockIdx.x * 256 + threadIdx.x;
    int d = idx & 255, j = idx >> 8;
    float val = src[(size_t)d * 256 + j];
    bf16 h16, l16; bsplit(val, h16, l16);
    dst[(size_t)j * 512 + d]       = h16;
    dst[(size_t)j * 512 + 256 + d] = l16;
}

__global__ void prep_so_kernel(const float* __restrict__ o) {
    int row  = (blockIdx.x * blockDim.x + threadIdx.x) >> 5;
    int lane = threadIdx.x & 31;
    const float* rp = o + (size_t)row * 256;
    float4 a = ((const float4*)rp)[lane];
    float4 b = ((const float4*)rp)[lane + 32];
    float s = a.x + a.y + a.z + a.w + b.x + b.y + b.z + b.w;
#pragma unroll
    for (int off = 16; off > 0; off >>= 1) s += __shfl_xor_sync(0xffffffffu, s, off);
    if (lane == 0) g_so[row] = s;
}

// ---------------- LN1 + block permute -> int8 2-level + per-row scale ----------------
__global__ void ln1_kernel(const float* __restrict__ in,
                           const float* __restrict__ gamma,
                           const float* __restrict__ beta) {
    int gwarp = (blockIdx.x * blockDim.x + threadIdx.x) >> 5;
    int lane  = threadIdx.x & 31;
    const float* row = in + (size_t)gwarp * DD;
    float4 v0 = ((const float4*)row)[lane];
    float4 v1 = ((const float4*)row)[lane + 32];
    float s  = v0.x + v0.y + v0.z + v0.w + v1.x + v1.y + v1.z + v1.w;
    float sq = v0.x*v0.x + v0.y*v0.y + v0.z*v0.z + v0.w*v0.w
             + v1.x*v1.x + v1.y*v1.y + v1.z*v1.z + v1.w*v1.w;
#pragma unroll
    for (int o = 16; o > 0; o >>= 1) {
        s  += __shfl_xor_sync(0xffffffffu, s,  o);
        sq += __shfl_xor_sync(0xffffffffu, sq, o);
    }
    float mean = s * (1.0f / 256.0f);
    float var  = sq * (1.0f / 256.0f) - mean * mean;
    float rstd = rsqrtf(var + 1e-5f);

    int b = gwarp >> 12, pos = gwarp & 4095;
    int h = pos >> 6, w = pos & 63;
    int m = ((h & 7) << 3) | (w & 7);
    int n = ((h >> 3) << 3) | (w >> 3);
    size_t orow = ((size_t)b << 12) | (unsigned)((m << 6) | n);

    float4 g0 = ((const float4*)gamma)[lane];
    float4 g1 = ((const float4*)gamma)[lane + 32];
    float4 b0 = ((const float4*)beta)[lane];
    float4 b1 = ((const float4*)beta)[lane + 32];
    float o8[8];
    o8[0] = (v0.x - mean) * rstd * g0.x + b0.x;
    o8[1] = (v0.y - mean) * rstd * g0.y + b0.y;
    o8[2] = (v0.z - mean) * rstd * g0.z + b0.z;
    o8[3] = (v0.w - mean) * rstd * g0.w + b0.w;
    o8[4] = (v1.x - mean) * rstd * g1.x + b1.x;
    o8[5] = (v1.y - mean) * rstd * g1.y + b1.y;
    o8[6] = (v1.z - mean) * rstd * g1.z + b1.z;
    o8[7] = (v1.w - mean) * rstd * g1.w + b1.w;

    float amax = 0.f;
#pragma unroll
    for (int i = 0; i < 8; i++) amax = fmaxf(amax, fabsf(o8[i]));
#pragma unroll
    for (int o = 16; o > 0; o >>= 1) amax = fmaxf(amax, __shfl_xor_sync(0xffffffffu, amax, o));
    amax = fmaxf(amax, 1e-20f);
    float inv = 127.0f / amax;
    if (lane == 0) g_asc[orow] = amax * (1.0f / 127.0f);

    int8_t* base = g_aq8 + orow * 512;
    // cols lane*4..+3 (o8[0..3]) and lane*4+128..+131 (o8[4..7])
    uint32_t p1a = 0, p2a = 0, p1b = 0, p2b = 0;
#pragma unroll
    for (int i = 0; i < 4; i++) {
        int i1, i2;
        q2(o8[i] * inv, i1, i2);
        p1a |= (uint32_t)(uint8_t)(int8_t)i1 << (i * 8);
        p2a |= (uint32_t)(uint8_t)(int8_t)i2 << (i * 8);
        q2(o8[4 + i] * inv, i1, i2);
        p1b |= (uint32_t)(uint8_t)(int8_t)i1 << (i * 8);
        p2b |= (uint32_t)(uint8_t)(int8_t)i2 << (i * 8);
    }
    *(uint32_t*)(base + lane * 4)             = p1a;
    *(uint32_t*)(base + lane * 4 + 128)       = p1b;
    *(uint32_t*)(base + 256 + lane * 4)       = p2a;
    *(uint32_t*)(base + 256 + lane * 4 + 128) = p2b;
}

// ================= QKV GEMM: int8 2-level, 128x128 tile, k=64 chunks =================
#define QP8 80                         // bytes per smem row: 64 k + 16 pad
#define Q_PL (128 * QP8)               // 10240 B per plane
#define Q_STG (4 * Q_PL)               // Ai1,Ai2,Bj1,Bj2 = 40960 B
#define QSMEM (2 * Q_STG)              // 81920 B

__global__ __launch_bounds__(256)
void qkv_gemm_kernel(const int8_t* __restrict__ Aq,
                     const int8_t* __restrict__ Bq,
                     bf16* __restrict__ Csp) {
    extern __shared__ int8_t smem8[];
    uint32_t sb = (uint32_t)__cvta_generic_to_shared(smem8);

    int tid = threadIdx.x;
    int lane = tid & 31, warp = tid >> 5;
    int wm = warp & 1, wn = warp >> 1;
    int g = lane >> 2, tig = lane & 3;
    int lrow8 = lane & 7, l8 = (lane >> 3) & 1, l16 = (lane >> 4) & 1;
    int rowBase = blockIdx.y * 128;
    int colBase = blockIdx.x * 128;

    uint32_t aoff = (uint32_t)((wm * 64 + lrow8 + 8 * l8) * QP8 + 16 * l16);
    uint32_t boff = (uint32_t)((wn * 32 + lrow8) * QP8 + 16 * l8);

    int acc0[4][4][4] = {};
    int acc1[4][4][4] = {};

    auto load_chunk = [&](int c, int st) {
        const int8_t* Ag = Aq + (size_t)rowBase * 512 + c * 64;
        const int8_t* Bg = Bq + (size_t)colBase * 512 + c * 64;
        uint32_t base = sb + (uint32_t)st * Q_STG;
#pragma unroll
        for (int i = 0; i < 2; i++) {
            int f = tid + i * 256;                 // 512 transfers per plane
            int r = f >> 2, qq = f & 3;            // 128 rows x 4 x16B
            uint32_t so = (uint32_t)(r * QP8 + qq * 16);
            const int8_t* ga = Ag + (size_t)r * 512 + qq * 16;
            const int8_t* gb = Bg + (size_t)r * 512 + qq * 16;
            cpasync16(base + so,            ga);
            cpasync16(base + Q_PL + so,     ga + 256);
            cpasync16(base + 2 * Q_PL + so, gb);
            cpasync16(base + 3 * Q_PL + so, gb + 256);
        }
        asm volatile("cp.async.commit_group;\n");
    };

    load_chunk(0, 0);
    const int NCH = 4;                  // K = 256 / 64
    for (int c = 0; c < NCH; c++) {
        if (c + 1 < NCH) {
            load_chunk(c + 1, (c + 1) & 1);
            asm volatile("cp.async.wait_group 1;\n");
        } else {
            asm volatile("cp.async.wait_group 0;\n");
        }
        __syncthreads();

        uint32_t stb = sb + (uint32_t)(c & 1) * Q_STG;
#pragma unroll
        for (int ks = 0; ks < 2; ks++) {           // 2 k32 steps per k64 chunk
            uint32_t kb = (uint32_t)ks * 32;
            uint32_t i1f[4][4], i2f[4][4];
#pragma unroll
            for (int mi = 0; mi < 4; mi++) {
                uint32_t a = stb + aoff + mi * (16 * QP8) + kb;
                ldsm_x4(i1f[mi], a);
                ldsm_x4(i2f[mi], a + Q_PL);
            }
            uint32_t j1f[4][2], j2f[4][2];
#pragma unroll
            for (int ni = 0; ni < 4; ni++) {
                uint32_t ba = stb + 2 * Q_PL + boff + ni * (8 * QP8) + kb;
                ldsm_x2(j1f[ni], ba);
                ldsm_x2(j2f[ni], ba + Q_PL);
            }
#pragma unroll
            for (int ni = 0; ni < 4; ni++)
#pragma unroll
                for (int mi = 0; mi < 4; mi++) mma_s8(acc0[mi][ni], i1f[mi], j1f[ni]);
#pragma unroll
            for (int ni = 0; ni < 4; ni++)
#pragma unroll
                for (int mi = 0; mi < 4; mi++) mma_s8(acc1[mi][ni], i1f[mi], j2f[ni]);
#pragma unroll
            for (int ni = 0; ni < 4; ni++)
#pragma unroll
                for (int mi = 0; mi < 4; mi++) mma_s8(acc1[mi][ni], i2f[mi], j1f[ni]);
        }
        __syncthreads();
    }

    // epilogue: dequant -> split bf16
#pragma unroll
    for (int mi = 0; mi < 4; mi++) {
        int r0 = rowBase + wm * 64 + mi * 16 + g;
        int r1 = r0 + 8;
        float sa0 = g_asc[r0], sa1 = g_asc[r1];
#pragma unroll
        for (int ni = 0; ni < 4; ni++) {
            int col = colBase + wn * 32 + ni * 8 + tig * 2;
            float sb0 = g_wsc[col], sb1 = g_wsc[col + 1];
            const float c254 = 1.0f / 254.0f;
            float v00 = sa0 * sb0 * ((float)acc0[mi][ni][0] + (float)acc1[mi][ni][0] * c254);
            float v01 = sa0 * sb1 * ((float)acc0[mi][ni][1] + (float)acc1[mi][ni][1] * c254);
            float v10 = sa1 * sb0 * ((float)acc0[mi][ni][2] + (float)acc1[mi][ni][2] * c254);
            float v11 = sa1 * sb1 * ((float)acc0[mi][ni][3] + (float)acc1[mi][ni][3] * c254);
            bf16 h0, l0, h1, l1;
            bsplit(v00, h0, l0); bsplit(v01, h1, l1);
            *(__nv_bfloat162*)(Csp + (size_t)r0 * 5120 + col)        = __nv_bfloat162(h0, h1);
            *(__nv_bfloat162*)(Csp + (size_t)r0 * 5120 + 2560 + col) = __nv_bfloat162(l0, l1);
            bsplit(v10, h0, l0); bsplit(v11, h1, l1);
            *(__nv_bfloat162*)(Csp + (size_t)r1 * 5120 + col)        = __nv_bfloat162(h0, h1);
            *(__nv_bfloat162*)(Csp + (size_t)r1 * 5120 + 2560 + col) = __nv_bfloat162(l0, l1);
        }
    }
}

// ================= fused MLP (R11, term-major) =================
#define WGP 40
#define A_PL (128 * WGP * 2)
#define B_PL (256 * WGP * 2)
#define WSTAGE (2 * A_PL + 2 * B_PL)
#define HP 264
#define HPLANE (128 * HP * 2)
#define W2S0 (2 * HPLANE)
#define W2STG (2 * B_PL)
#define MLPSMEM (W2S0 + 2 * W2STG)

__global__ __launch_bounds__(256, 1)
void mlp_fused_kernel(const bf16* __restrict__ ln2sp,
                      const bf16* __restrict__ w1sp,
                      const bf16* __restrict__ w2sp,
                      const float* __restrict__ b1,
                      const float* __restrict__ b2,
                      const float* __restrict__ x2,
                      float* __restrict__ out) {
    extern __shared__ bf16 smem[];
    uint32_t sb = (uint32_t)__cvta_generic_to_shared(smem);

    int tid = threadIdx.x;
    int lane = tid & 31, warp = tid >> 5;
    int wm = warp & 1, wn = warp >> 1;
    int g = lane >> 2, tig = lane & 3;
    int lrow8 = lane & 7, l8 = (lane >> 3) & 1, l16 = (lane >> 4) & 1;
    int rowBase = blockIdx.x * 128;

    uint32_t aoff = (uint32_t)(((wm * 64 + lrow8 + 8 * l8) * WGP + 8 * l16) * 2);
    uint32_t boff = (uint32_t)(((wn * 64 + lrow8) * WGP + 8 * l8) * 2);
    uint32_t hoff = (uint32_t)(((wm * 64 + lrow8 + 8 * l8) * HP + 8 * l16) * 2);

    float acc[4][8][4] = {};

    auto load1 = [&](int c, int st) {
        const bf16* Ag = ln2sp + (size_t)rowBase * 512 + c * 32;
        const bf16* Bg = w1sp + c * 32;
        uint32_t base = sb + (uint32_t)st * WSTAGE;
#pragma unroll
        for (int i = 0; i < 2; i++) {
            int f = tid + i * 256;
            int r = f >> 2, q = f & 3;
            uint32_t so = (uint32_t)(r * WGP + q * 8) * 2;
            const bf16* ga = Ag + (size_t)r * 512 + q * 8;
            cpasync16(base + so,        ga);
            cpasync16(base + A_PL + so, ga + 256);
        }
#pragma unroll
        for (int i = 0; i < 4; i++) {
            int f = tid + i * 256;
            int r = f >> 2, q = f & 3;
            uint32_t so = (uint32_t)(r * WGP + q * 8) * 2;
            const bf16* gb = Bg + (size_t)r * 512 + q * 8;
            cpasync16(base + 2 * A_PL + so,        gb);
            cpasync16(base + 2 * A_PL + B_PL + so, gb + 256);
        }
        asm volatile("cp.async.commit_group;\n");
    };
    auto load2 = [&](int c, int st) {
        const bf16* Bg = w2sp + c * 32;
        uint32_t base = sb + W2S0 + (uint32_t)st * W2STG;
#pragma unroll
        for (int i = 0; i < 4; i++) {
            int f = tid + i * 256;
            int r = f >> 2, q = f & 3;
            uint32_t so = (uint32_t)(r * WGP + q * 8) * 2;
            const bf16* gb = Bg + (size_t)r * 512 + q * 8;
            cpasync16(base + so,        gb);
            cpasync16(base + B_PL + so, gb + 256);
        }
        asm volatile("cp.async.commit_group;\n");
    };

    load1(0, 0);
    for (int c = 0; c < 8; c++) {
        if (c + 1 < 8) {
            load1(c + 1, (c + 1) & 1);
            asm volatile("cp.async.wait_group 1;\n");
        } else {
            asm volatile("cp.async.wait_group 0;\n");
        }
        __syncthreads();
        uint32_t stb = sb + (uint32_t)(c & 1) * WSTAGE;
#pragma unroll
        for (int ks = 0; ks < 2; ks++) {
            uint32_t kb2 = ks * 32;
            uint32_t ahi[4][4], alo[4][4];
#pragma unroll
            for (int mi = 0; mi < 4; mi++) {
                uint32_t a = stb + aoff + mi * (16 * WGP * 2) + kb2;
                ldsm_x4(ahi[mi], a);
                ldsm_x4(alo[mi], a + A_PL);
            }
#pragma unroll
            for (int ni = 0; ni < 8; ni++) {
                uint32_t ba = stb + 2 * A_PL + boff + ni * (8 * WGP * 2) + kb2;
                uint32_t bh[2], bl[2];
                ldsm_x2(bh, ba);
                ldsm_x2(bl, ba + B_PL);
#pragma unroll
                for (int mi = 0; mi < 4; mi++) mma16816(acc[mi][ni], ahi[mi], bh);
#pragma unroll
                for (int mi = 0; mi < 4; mi++) mma16816(acc[mi][ni], alo[mi], bh);
#pragma unroll
                for (int mi = 0; mi < 4; mi++) mma16816(acc[mi][ni], ahi[mi], bl);
            }
        }
        __syncthreads();
    }

    load2(0, 0);

    bf16* hhi = smem;
    bf16* hlo = smem + 128 * HP;
#pragma unroll
    for (int mi = 0; mi < 4; mi++) {
        int r0 = wm * 64 + mi * 16 + g;
        int r1 = r0 + 8;
#pragma unroll
        for (int ni = 0; ni < 8; ni++) {
            int col = wn * 64 + ni * 8 + tig * 2;
            float2 bv = *(const float2*)(b1 + col);
            float v0 = fmaxf(acc[mi][ni][0] + bv.x, 0.f);
            float v1 = fmaxf(acc[mi][ni][1] + bv.y, 0.f);
            float v2 = fmaxf(acc[mi][ni][2] + bv.x, 0.f);
            float v3 = fmaxf(acc[mi][ni][3] + bv.y, 0.f);
            bf16 h0, l0, h1, l1;
            bsplit(v0, h0, l0); bsplit(v1, h1, l1);
            *(__nv_bfloat162*)(hhi + r0 * HP + col) = __nv_bfloat162(h0, h1);
            *(__nv_bfloat162*)(hlo + r0 * HP + col) = __nv_bfloat162(l0, l1);
            bsplit(v2, h0, l0); bsplit(v3, h1, l1);
            *(__nv_bfloat162*)(hhi + r1 * HP + col) = __nv_bfloat162(h0, h1);
            *(__nv_bfloat162*)(hlo + r1 * HP + col) = __nv_bfloat162(l0, l1);
            acc[mi][ni][0] = 0.f; acc[mi][ni][1] = 0.f;
            acc[mi][ni][2] = 0.f; acc[mi][ni][3] = 0.f;
        }
    }
    __syncthreads();

    for (int c = 0; c < 8; c++) {
        if (c + 1 < 8) {
            load2(c + 1, (c + 1) & 1);
            asm volatile("cp.async.wait_group 1;\n");
        } else {
            asm volatile("cp.async.wait_group 0;\n");
        }
        __syncthreads();
        uint32_t w2b = sb + W2S0 + (uint32_t)(c & 1) * W2STG;
#pragma unroll
        for (int ks = 0; ks < 2; ks++) {
            uint32_t kbyte = (uint32_t)((c * 32 + ks * 16) * 2);
            uint32_t kb2 = ks * 32;
            uint32_t ahi[4][4], alo[4][4];
#pragma unroll
            for (int mi = 0; mi < 4; mi++) {
                uint32_t a = sb + hoff + mi * (16 * HP * 2) + kbyte;
                ldsm_x4(ahi[mi], a);
                ldsm_x4(alo[mi], a + HPLANE);
            }
#pragma unroll
            for (int ni = 0; ni < 8; ni++) {
                uint32_t ba = w2b + boff + ni * (8 * WGP * 2) + kb2;
                uint32_t bh[2], bl[2];
                ldsm_x2(bh, ba);
                ldsm_x2(bl, ba + B_PL);
#pragma unroll
                for (int mi = 0; mi < 4; mi++) mma16816(acc[mi][ni], ahi[mi], bh);
#pragma unroll
                for (int mi = 0; mi < 4; mi++) mma16816(acc[mi][ni], alo[mi], bh);
#pragma unroll
                for (int mi = 0; mi < 4; mi++) mma16816(acc[mi][ni], ahi[mi], bl);
            }
        }
        __syncthreads();
    }

#pragma unroll
    for (int mi = 0; mi < 4; mi++) {
        int r0 = rowBase + wm * 64 + mi * 16 + g;
        int r1 = r0 + 8;
#pragma unroll
        for (int ni = 0; ni < 8; ni++) {
            int col = wn * 64 + ni * 8 + tig * 2;
            float2 bv = *(const float2*)(b2 + col);
            float2 e0 = *(const float2*)(x2 + (size_t)r0 * DD + col);
            float2 e1 = *(const float2*)(x2 + (size_t)r1 * DD + col);
            float2 v0 = make_float2(acc[mi][ni][0] + bv.x + e0.x,
                                    acc[mi][ni][1] + bv.y + e0.y);
            float2 v1 = make_float2(acc[mi][ni][2] + bv.x + e1.x,
                                    acc[mi][ni][3] + bv.y + e1.y);
            *(float2*)(out + (size_t)r0 * DD + col) = v0;
            *(float2*)(out + (size_t)r1 * DD + col) = v1;
        }
    }
}

// ================= tensor-core attention + fused head-mix (R11) =================
#define TP 264
#define PP 72
#define TILE_E (64 * TP)
#define TEB (TILE_E * 2)
#define PPB (64 * PP * 2)
#define ATTN_SMEM_B (6 * TEB + 2 * PPB + 1024)

__global__ __launch_bounds__(256)
void attn_mma_kernel() {
    extern __shared__ bf16 asm_[];
    bf16* Ph = asm_ + 6 * TILE_E;
    bf16* Pl = Ph + 64 * PP;
    float* stmax = (float*)(Pl + 64 * PP);
    float* stsum = stmax + 128;
    uint32_t sbase = (uint32_t)__cvta_generic_to_shared(asm_);

    int tid = threadIdx.x;
    int lane = tid & 31, warp = tid >> 5;
    int g = lane >> 2, tig = lane & 3;
    int lrow8 = lane & 7, l8 = (lane >> 3) & 1, l16 = (lane >> 4) & 1;

    int u = blockIdx.x;
    bool gridmode = (u < 512);
    int b, fix;
    if (gridmode) { b = u >> 6; fix = u & 63; }
    else          { int u2 = u - 512; b = u2 >> 6; fix = u2 & 63; }
    size_t base; int stride;
    if (gridmode) { base = (size_t)b * 4096 + fix; stride = 64; }
    else          { base = (size_t)b * 4096 + (size_t)fix * 64; stride = 1; }
    int head0 = gridmode ? 0 : 4;

    auto load_piece = [&](int planeIdx, int colOff) {
        uint32_t sh = sbase + (uint32_t)planeIdx * TEB;
#pragma unroll
        for (int i = 0; i < 8; i++) {
            int f = i * 256 + tid;
            int r = f >> 5, q = f & 31;
            size_t token = base + (size_t)r * stride;
            const bf16* ga = g_qkvsp + token * 5120 + colOff + q * 8;
            uint32_t so = (uint32_t)(r * TP + q * 8) * 2;
            cpasync16(sh + so, ga);
            cpasync16(sh + TEB + so, ga + 2560);
        }
    };

    load_piece(2, 2048);
    load_piece(4, 2304);
    load_piece(0, head0 * 256);
    asm volatile("cp.async.commit_group;\n");
    asm volatile("cp.async.wait_group 0;\n");
    __syncthreads();

    int warpm = warp >> 1, warpn = warp & 1;
    int row0 = warpm * 16 + g, row1 = row0 + 8;

    uint32_t qoff = (uint32_t)(((warpm * 16 + lrow8 + 8 * l8) * TP + 8 * l16) * 2);
    uint32_t koff = (uint32_t)(((warpn * 32 + lrow8) * TP + 8 * l8) * 2);
    uint32_t poff = (uint32_t)(((warpm * 16 + lrow8 + 8 * l8) * PP + 8 * l16) * 2);
    uint32_t voff = (uint32_t)(((lrow8 + 8 * l8) * TP) * 2);
    uint32_t PB = sbase + 6 * TEB;
    uint32_t KB = sbase + 2 * TEB;
    uint32_t VB = sbase + 4 * TEB;

    float zacc[16][4] = {};

    for (int hl = 0; hl < 4; hl++) {
        int head = head0 + hl;

        float c[4][4] = {};
#pragma unroll 4
        for (int ks = 0; ks < 16; ks++) {
            uint32_t kb2 = ks * 32;
            uint32_t ahi[4], alo[4];
            ldsm_x4(ahi, sbase + qoff + kb2);
            ldsm_x4(alo, sbase + TEB + qoff + kb2);
            uint32_t bh[4][2], bl[4][2];
#pragma unroll
            for (int ni = 0; ni < 4; ni++) {
                uint32_t ba = KB + koff + ni * (8 * TP * 2) + kb2;
                ldsm_x2(bh[ni], ba);
                ldsm_x2(bl[ni], ba + TEB);
            }
#pragma unroll
            for (int ni = 0; ni < 4; ni++) mma16816(c[ni], ahi, bh[ni]);
#pragma unroll
            for (int ni = 0; ni < 4; ni++) mma16816(c[ni], alo, bh[ni]);
#pragma unroll
            for (int ni = 0; ni < 4; ni++) mma16816(c[ni], ahi, bl[ni]);
        }

        float m0 = -1e30f, m1 = -1e30f;
#pragma unroll
        for (int ni = 0; ni < 4; ni++) {
            m0 = fmaxf(m0, fmaxf(c[ni][0], c[ni][1]));
            m1 = fmaxf(m1, fmaxf(c[ni][2], c[ni][3]));
        }
        m0 = fmaxf(m0, __shfl_xor_sync(0xffffffffu, m0, 1));
        m0 = fmaxf(m0, __shfl_xor_sync(0xffffffffu, m0, 2));
        m1 = fmaxf(m1, __shfl_xor_sync(0xffffffffu, m1, 1));
        m1 = fmaxf(m1, __shfl_xor_sync(0xffffffffu, m1, 2));
        if (tig == 0) {
            stmax[row0 * 2 + warpn] = m0;
            stmax[row1 * 2 + warpn] = m1;
        }
        __syncthreads();
        m0 = fmaxf(stmax[row0 * 2], stmax[row0 * 2 + 1]);
        m1 = fmaxf(stmax[row1 * 2], stmax[row1 * 2 + 1]);
        float s0 = 0.f, s1 = 0.f;
#pragma unroll
        for (int ni = 0; ni < 4; ni++) {
            c[ni][0] = __expf(c[ni][0] - m0);
            c[ni][1] = __expf(c[ni][1] - m0);
            c[ni][2] = __expf(c[ni][2] - m1);
            c[ni][3] = __expf(c[ni][3] - m1);
            s0 += c[ni][0] + c[ni][1];
            s1 += c[ni][2] + c[ni][3];
        }
        s0 += __shfl_xor_sync(0xffffffffu, s0, 1);
        s0 += __shfl_xor_sync(0xffffffffu, s0, 2);
        s1 += __shfl_xor_sync(0xffffffffu, s1, 1);
        s1 += __shfl_xor_sync(0xffffffffu, s1, 2);
        if (tig == 0) {
            stsum[row0 * 2 + warpn] = s0;
            stsum[row1 * 2 + warpn] = s1;
        }
        __syncthreads();
        float inv0 = 1.0f / (stsum[row0 * 2] + stsum[row0 * 2 + 1]);
        float inv1 = 1.0f / (stsum[row1 * 2] + stsum[row1 * 2 + 1]);
#pragma unroll
        for (int ni = 0; ni < 4; ni++) {
            int cn = warpn * 32 + ni * 8 + 2 * tig;
            bf16 h0, l0, h1, l1;
            bsplit(c[ni][0] * inv0, h0, l0); bsplit(c[ni][1] * inv0, h1, l1);
            *(__nv_bfloat162*)(Ph + row0 * PP + cn) = __nv_bfloat162(h0, h1);
            *(__nv_bfloat162*)(Pl + row0 * PP + cn) = __nv_bfloat162(l0, l1);
            bsplit(c[ni][2] * inv1, h0, l0); bsplit(c[ni][3] * inv1, h1, l1);
            *(__nv_bfloat162*)(Ph + row1 * PP + cn) = __nv_bfloat162(h0, h1);
            *(__nv_bfloat162*)(Pl + row1 * PP + cn) = __nv_bfloat162(l0, l1);
        }
        __syncthreads();

        if (hl < 3) {
            load_piece(0, (head + 1) * 256);
            asm volatile("cp.async.commit_group;\n");
        }

        const float* sop = g_so + head * 256;
#pragma unroll
        for (int ks = 0; ks < 4; ks++) {
            uint32_t kb2 = ks * 32;
            uint32_t ph[4], pl[4];
            ldsm_x4(ph, PB + poff + kb2);
            ldsm_x4(pl, PB + PPB + poff + kb2);
            uint32_t vrow = VB + voff + (uint32_t)ks * (16 * TP * 2);
#pragma unroll
            for (int ni = 0; ni < 16; ni++) {
                uint32_t va = vrow + (uint32_t)((warpn * 128 + ni * 8) * 2);
                uint32_t bh[2], bl[2];
                ldsm_x2t(bh, va);
                ldsm_x2t(bl, va + TEB);
                float ot[4] = {};
                mma16816(ot, ph, bh);
                mma16816(ot, pl, bh);
                mma16816(ot, ph, bl);
                float2 sv = *(const float2*)(sop + warpn * 128 + ni * 8 + 2 * tig);
                zacc[ni][0] += ot[0] * sv.x; zacc[ni][1] += ot[1] * sv.y;
                zacc[ni][2] += ot[2] * sv.x; zacc[ni][3] += ot[3] * sv.y;
            }
        }

        if (hl < 3) asm volatile("cp.async.wait_group 0;\n");
        __syncthreads();
    }

    float* gz = gridmode ? g_z1 : g_z2;
    size_t tok0 = base + (size_t)row0 * stride;
    size_t tok1 = base + (size_t)row1 * stride;
#pragma unroll
    for (int ni = 0; ni < 16; ni++) {
        int col = warpn * 128 + ni * 8 + 2 * tig;
        *(float2*)(gz + tok0 * DD + col) = make_float2(zacc[ni][0], zacc[ni][1]);
        *(float2*)(gz + tok1 * DD + col) = make_float2(zacc[ni][2], zacc[ni][3]);
    }
}

// ---------- z1+z2 + unpermute + residual + LN2 -> split bf16 ----------
__device__ __forceinline__ void store_split8(bf16* rowp, int col, float4 v0, float4 v1) {
    bf16 h[8], l[8];
    bsplit(v0.x, h[0], l[0]); bsplit(v0.y, h[1], l[1]);
    bsplit(v0.z, h[2], l[2]); bsplit(v0.w, h[3], l[3]);
    bsplit(v1.x, h[4], l[4]); bsplit(v1.y, h[5], l[5]);
    bsplit(v1.z, h[6], l[6]); bsplit(v1.w, h[7], l[7]);
#pragma unroll
    for (int i = 0; i < 4; i++) {
        rowp[col + i]             = h[i];
        rowp[col + 128 + i]       = h[4 + i];
        rowp[256 + col + i]       = l[i];
        rowp[256 + col + 128 + i] = l[4 + i];
    }
}

__global__ void zred_ln2_kernel(const float* __restrict__ x,
                                const float* __restrict__ gamma,
                                const float* __restrict__ beta,
                                float* __restrict__ x2) {
    int gw   = (blockIdx.x * blockDim.x + threadIdx.x) >> 5;
    int lane = threadIdx.x & 31;

    int b = gw >> 12, m = (gw >> 6) & 63, n = gw & 63;
    int hh = ((n >> 3) << 3) | (m >> 3);
    int ww = ((n & 7) << 3) | (m & 7);
    size_t orow = ((size_t)b << 12) | (unsigned)((hh << 6) | ww);

    const float* z1 = g_z1 + (size_t)gw * DD;
    const float* z2 = g_z2 + (size_t)gw * DD;
    float4 a0 = ((const float4*)z1)[lane];
    float4 a1 = ((const float4*)z1)[lane + 32];
    float4 b0v = ((const float4*)z2)[lane];
    float4 b1v = ((const float4*)z2)[lane + 32];
    const float* xr = x + orow * DD;
    float4 x0 = ((const float4*)xr)[lane];
    float4 x1 = ((const float4*)xr)[lane + 32];
    float4 v0 = make_float4(x0.x + a0.x + b0v.x, x0.y + a0.y + b0v.y,
                            x0.z + a0.z + b0v.z, x0.w + a0.w + b0v.w);
    float4 v1 = make_float4(x1.x + a1.x + b1v.x, x1.y + a1.y + b1v.y,
                            x1.z + a1.z + b1v.z, x1.w + a1.w + b1v.w);

    ((float4*)(x2 + orow * DD))[lane]      = v0;
    ((float4*)(x2 + orow * DD))[lane + 32] = v1;

    float s  = v0.x + v0.y + v0.z + v0.w + v1.x + v1.y + v1.z + v1.w;
    float sq = v0.x*v0.x + v0.y*v0.y + v0.z*v0.z + v0.w*v0.w
             + v1.x*v1.x + v1.y*v1.y + v1.z*v1.z + v1.w*v1.w;
#pragma unroll
    for (int o = 16; o > 0; o >>= 1) {
        s  += __shfl_xor_sync(0xffffffffu, s,  o);
        sq += __shfl_xor_sync(0xffffffffu, sq, o);
    }
    float mean = s * (1.0f / 256.0f);
    float var  = sq * (1.0f / 256.0f) - mean * mean;
    float rstd = rsqrtf(var + 1e-5f);

    float4 g0 = ((const float4*)gamma)[lane];
    float4 g1 = ((const float4*)gamma)[lane + 32];
    float4 bb0 = ((const float4*)beta)[lane];
    float4 bb1 = ((const float4*)beta)[lane + 32];
    float4 o0, o1;
    o0.x = (v0.x - mean) * rstd * g0.x + bb0.x;
    o0.y = (v0.y - mean) * rstd * g0.y + bb0.y;
    o0.z = (v0.z - mean) * rstd * g0.z + bb0.z;
    o0.w = (v0.w - mean) * rstd * g0.w + bb0.w;
    o1.x = (v1.x - mean) * rstd * g1.x + bb1.x;
    o1.y = (v1.y - mean) * rstd * g1.y + bb1.y;
    o1.z = (v1.z - mean) * rstd * g1.z + bb1.z;
    o1.w = (v1.w - mean) * rstd * g1.w + bb1.w;
    store_split8(g_ln2sp + orow * 512, lane * 4, o0, o1);
}

// ---------------- launch ----------------
extern "C" void kernel_launch(void* const* d_in, const int* in_sizes, int n_in,
                              void* d_out, int out_size) {
    const float* x    = (const float*)d_in[0];
    const float* ln1w = (const float*)d_in[1];
    const float* ln1b = (const float*)d_in[2];
    const float* qw   = (const float*)d_in[3];
    const float* kw   = (const float*)d_in[4];
    const float* vw   = (const float*)d_in[5];
    const float* ow   = (const float*)d_in[6];
    const float* ln2w = (const float*)d_in[7];
    const float* ln2b = (const float*)d_in[8];
    const float* w1   = (const float*)d_in[9];
    const float* b1   = (const float*)d_in[10];
    const float* w2   = (const float*)d_in[11];
    const float* b2   = (const float*)d_in[12];
    float* out = (float*)d_out;

    int8_t *p_aq8, *p_wq8;
    bf16 *p_w1sp, *p_w2sp, *p_ln2sp, *p_qkvsp;
    float *p_x2;
    cudaGetSymbolAddress((void**)&p_aq8,   g_aq8);
    cudaGetSymbolAddress((void**)&p_wq8,   g_wq8);
    cudaGetSymbolAddress((void**)&p_w1sp,  g_w1sp);
    cudaGetSymbolAddress((void**)&p_w2sp,  g_w2sp);
    cudaGetSymbolAddress((void**)&p_ln2sp, g_ln2sp);
    cudaGetSymbolAddress((void**)&p_qkvsp, g_qkvsp);
    cudaGetSymbolAddress((void**)&p_x2,    g_x2);

    cudaFuncSetAttribute(attn_mma_kernel, cudaFuncAttributeMaxDynamicSharedMemorySize,
                         ATTN_SMEM_B);
    cudaFuncSetAttribute(qkv_gemm_kernel, cudaFuncAttributeMaxDynamicSharedMemorySize, QSMEM);
    cudaFuncSetAttribute(mlp_fused_kernel, cudaFuncAttributeMaxDynamicSharedMemorySize, MLPSMEM);

    // launch #4 = QKV GEMM (profiled by ncu -s 5 -c 1)
    prep_wqkv_q8<<<QKVC / 8, 256>>>(qw, kw, vw);                       // 1
    ln1_kernel<<<NTOK / 8, 256>>>(x, ln1w, ln1b);                      // 2
    prep_wt_kernel<<<256, 256>>>(w1, p_w1sp);                          // 3
    qkv_gemm_kernel<<<dim3(QKVC / 128, NTOK / 128), 256, QSMEM>>>(     // 4
        p_aq8, p_wq8, p_qkvsp);
    prep_so_kernel<<<256, 256>>>(ow);                                  // 5
    prep_wt_kernel<<<256, 256>>>(w2, p_w2sp);                          // 6
    attn_mma_kernel<<<1024, 256, ATTN_SMEM_B>>>();                     // 7
    zred_ln2_kernel<<<NTOK / 8, 256>>>(x, ln2w, ln2b, p_x2);           // 8
    mlp_fused_kernel<<<NTOK / 128, 256, MLPSMEM>>>(                    // 9
        p_ln2sp, p_w1sp, p_w2sp, b1, b2, p_x2, out);
}

// round 14
// speedup vs baseline: 1.7330x; 1.7330x over previous
#include <cuda_runtime.h>
#include <cuda_bf16.h>
#include <cstdint>
#include <cstddef>

typedef __nv_bfloat16 bf16;

// ---------------- problem constants ----------------
#define NTOK     32768
#define DD       256
#define QKVC     2560

// ---------------- static scratch ----------------
__device__ bf16 g_asp  [(size_t)NTOK * 512];
__device__ bf16 g_wsp  [(size_t)QKVC * 512];
__device__ bf16 g_w1sp [(size_t)DD * 512];
__device__ bf16 g_w2sp [(size_t)DD * 512];
__device__ bf16 g_ln2sp[(size_t)NTOK * 512];
__device__ bf16 g_qkvsp[(size_t)NTOK * 5120];
__device__ float g_z1  [(size_t)NTOK * DD];
__device__ float g_z2  [(size_t)NTOK * DD];
__device__ float g_so  [2048];
__device__ float g_x2  [(size_t)NTOK * DD];

// ---------------- helpers ----------------
__device__ __forceinline__ void bsplit(float v, bf16& h, bf16& l) {
    h = __float2bfloat16_rn(v);
    l = __float2bfloat16_rn(v - __bfloat162float(h));
}
__device__ __forceinline__ void cpasync16(uint32_t s, const void* g) {
    asm volatile("cp.async.cg.shared.global [%0], [%1], 16;\n" :: "r"(s), "l"(g));
}
__device__ __forceinline__ void mma16816(float* c, const uint32_t* a, const uint32_t* b) {
    asm volatile(
        "mma.sync.aligned.m16n8k16.row.col.f32.bf16.bf16.f32 "
        "{%0,%1,%2,%3},{%4,%5,%6,%7},{%8,%9},{%0,%1,%2,%3};\n"
        : "+f"(c[0]), "+f"(c[1]), "+f"(c[2]), "+f"(c[3])
        : "r"(a[0]), "r"(a[1]), "r"(a[2]), "r"(a[3]), "r"(b[0]), "r"(b[1]));
}
__device__ __forceinline__ void ldsm_x4(uint32_t* r, uint32_t a) {
    asm volatile("ldmatrix.sync.aligned.m8n8.x4.shared.b16 {%0,%1,%2,%3}, [%4];"
        : "=r"(r[0]), "=r"(r[1]), "=r"(r[2]), "=r"(r[3]) : "r"(a));
}
__device__ __forceinline__ void ldsm_x2(uint32_t* r, uint32_t a) {
    asm volatile("ldmatrix.sync.aligned.m8n8.x2.shared.b16 {%0,%1}, [%2];"
        : "=r"(r[0]), "=r"(r[1]) : "r"(a));
}
__device__ __forceinline__ void ldsm_x2t(uint32_t* r, uint32_t a) {
    asm volatile("ldmatrix.sync.aligned.m8n8.x2.trans.shared.b16 {%0,%1}, [%2];"
        : "=r"(r[0]), "=r"(r[1]) : "r"(a));
}

// ---------------- weight prep ----------------
__global__ void prep_wqkv_kernel(const float* __restrict__ q,
                                 const float* __restrict__ k,
                                 const float* __restrict__ v) {
    int idx = blockIdx.x * 256 + threadIdx.x;
    int d = idx & 255, j = idx >> 8;
    float val;
    if (j < 2048) { int h = j >> 8, kk = j & 255; val = q[((size_t)(h * 256 + d)) * 256 + kk]; }
    else if (j < 2304) val = k[(size_t)d * 256 + (j - 2048)];
    else               val = v[(size_t)d * 256 + (j - 2304)];
    bf16 h16, l16; bsplit(val, h16, l16);
    g_wsp[(size_t)j * 512 + d]       = h16;
    g_wsp[(size_t)j * 512 + 256 + d] = l16;
}

__global__ void prep_wt_kernel(const float* __restrict__ src, bf16* __restrict__ dst) {
    int idx = blockIdx.x * 256 + threadIdx.x;
    int d = idx & 255, j = idx >> 8;
    float val = src[(size_t)d * 256 + j];
    bf16 h16, l16; bsplit(val, h16, l16);
    dst[(size_t)j * 512 + d]       = h16;
    dst[(size_t)j * 512 + 256 + d] = l16;
}

__global__ void prep_so_kernel(const float* __restrict__ o) {
    int row  = (blockIdx.x * blockDim.x + threadIdx.x) >> 5;
    int lane = threadIdx.x & 31;
    const float* rp = o + (size_t)row * 256;
    float4 a = ((const float4*)rp)[lane];
    float4 b = ((const float4*)rp)[lane + 32];
    float s = a.x + a.y + a.z + a.w + b.x + b.y + b.z + b.w;
#pragma unroll
    for (int off = 16; off > 0; off >>= 1) s += __shfl_xor_sync(0xffffffffu, s, off);
    if (lane == 0) g_so[row] = s;
}

// ---------------- LN1 + block permute -> split bf16 ----------------
__device__ __forceinline__ void store_split8(bf16* rowp, int col, float4 v0, float4 v1) {
    bf16 h[8], l[8];
    bsplit(v0.x, h[0], l[0]); bsplit(v0.y, h[1], l[1]);
    bsplit(v0.z, h[2], l[2]); bsplit(v0.w, h[3], l[3]);
    bsplit(v1.x, h[4], l[4]); bsplit(v1.y, h[5], l[5]);
    bsplit(v1.z, h[6], l[6]); bsplit(v1.w, h[7], l[7]);
#pragma unroll
    for (int i = 0; i < 4; i++) {
        rowp[col + i]             = h[i];
        rowp[col + 128 + i]       = h[4 + i];
        rowp[256 + col + i]       = l[i];
        rowp[256 + col + 128 + i] = l[4 + i];
    }
}

__global__ void ln1_kernel(const float* __restrict__ in,
                           const float* __restrict__ gamma,
                           const float* __restrict__ beta) {
    int gwarp = (blockIdx.x * blockDim.x + threadIdx.x) >> 5;
    int lane  = threadIdx.x & 31;
    const float* row = in + (size_t)gwarp * DD;
    float4 v0 = ((const float4*)row)[lane];
    float4 v1 = ((const float4*)row)[lane + 32];
    float s  = v0.x + v0.y + v0.z + v0.w + v1.x + v1.y + v1.z + v1.w;
    float sq = v0.x*v0.x + v0.y*v0.y + v0.z*v0.z + v0.w*v0.w
             + v1.x*v1.x + v1.y*v1.y + v1.z*v1.z + v1.w*v1.w;
#pragma unroll
    for (int o = 16; o > 0; o >>= 1) {
        s  += __shfl_xor_sync(0xffffffffu, s,  o);
        sq += __shfl_xor_sync(0xffffffffu, sq, o);
    }
    float mean = s * (1.0f / 256.0f);
    float var  = sq * (1.0f / 256.0f) - mean * mean;
    float rstd = rsqrtf(var + 1e-5f);

    int b = gwarp >> 12, pos = gwarp & 4095;
    int h = pos >> 6, w = pos & 63;
    int m = ((h & 7) << 3) | (w & 7);
    int n = ((h >> 3) << 3) | (w >> 3);
    size_t orow = ((size_t)b << 12) | (unsigned)((m << 6) | n);

    float4 g0 = ((const float4*)gamma)[lane];
    float4 g1 = ((const float4*)gamma)[lane + 32];
    float4 b0 = ((const float4*)beta)[lane];
    float4 b1 = ((const float4*)beta)[lane + 32];
    float4 o0, o1;
    o0.x = (v0.x - mean) * rstd * g0.x + b0.x;
    o0.y = (v0.y - mean) * rstd * g0.y + b0.y;
    o0.z = (v0.z - mean) * rstd * g0.z + b0.z;
    o0.w = (v0.w - mean) * rstd * g0.w + b0.w;
    o1.x = (v1.x - mean) * rstd * g1.x + b1.x;
    o1.y = (v1.y - mean) * rstd * g1.y + b1.y;
    o1.z = (v1.z - mean) * rstd * g1.z + b1.z;
    o1.w = (v1.w - mean) * rstd * g1.w + b1.w;
    store_split8(g_asp + orow * 512, lane * 4, o0, o1);
}

// ================= QKV GEMM: 128x128 tile, term-major 3-split (R11-proven) =================
#define GP 40
#define MATB (128 * GP * 2)            // 10240 B
#define STAGEB (4 * MATB)              // 40960 B
#define GSMEM (2 * STAGEB)             // 81920 B

__global__ __launch_bounds__(256, 2)
void qkv_gemm_kernel(const bf16* __restrict__ Asp,
                     const bf16* __restrict__ Bsp,
                     bf16* __restrict__ Csp) {
    extern __shared__ bf16 smem[];
    uint32_t sb = (uint32_t)__cvta_generic_to_shared(smem);

    int tid = threadIdx.x;
    int lane = tid & 31, warp = tid >> 5;
    int wm = warp & 1, wn = warp >> 1;
    int g = lane >> 2, tig = lane & 3;
    int lrow8 = lane & 7, l8 = (lane >> 3) & 1, l16 = (lane >> 4) & 1;
    int rowBase = blockIdx.y * 128;
    int colBase = blockIdx.x * 128;

    uint32_t aoff = (uint32_t)(((wm * 64 + lrow8 + 8 * l8) * GP + 8 * l16) * 2);
    uint32_t boff = (uint32_t)(((wn * 32 + lrow8) * GP + 8 * l8) * 2);

    float acc[4][4][4] = {};

    auto load_chunk = [&](int c, int st) {
        const bf16* Ag = Asp + (size_t)rowBase * 512 + c * 32;
        const bf16* Bg = Bsp + (size_t)colBase * 512 + c * 32;
        uint32_t base = sb + (uint32_t)st * STAGEB;
#pragma unroll
        for (int i = 0; i < 2; i++) {
            int f = tid + i * 256;
            int r = f >> 2, q = f & 3;
            uint32_t so = (uint32_t)(r * GP + q * 8) * 2;
            const bf16* ga = Ag + (size_t)r * 512 + q * 8;
            const bf16* gb = Bg + (size_t)r * 512 + q * 8;
            cpasync16(base + so,            ga);
            cpasync16(base + MATB + so,     ga + 256);
            cpasync16(base + 2 * MATB + so, gb);
            cpasync16(base + 3 * MATB + so, gb + 256);
        }
        asm volatile("cp.async.commit_group;\n");
    };

    load_chunk(0, 0);
    const int NCH = 8;
    for (int c = 0; c < NCH; c++) {
        if (c + 1 < NCH) {
            load_chunk(c + 1, (c + 1) & 1);
            asm volatile("cp.async.wait_group 1;\n");
        } else {
            asm volatile("cp.async.wait_group 0;\n");
        }
        __syncthreads();

        uint32_t stb = sb + (uint32_t)(c & 1) * STAGEB;
#pragma unroll
        for (int ks = 0; ks < 2; ks++) {
            uint32_t kb2 = ks * 32;
            uint32_t ahi[4][4], alo[4][4];
#pragma unroll
            for (int mi = 0; mi < 4; mi++) {
                uint32_t a = stb + aoff + mi * (16 * GP * 2) + kb2;
                ldsm_x4(ahi[mi], a);
                ldsm_x4(alo[mi], a + MATB);
            }
#pragma unroll
            for (int ni = 0; ni < 4; ni++) {
                uint32_t ba = stb + 2 * MATB + boff + ni * (8 * GP * 2) + kb2;
                uint32_t bh[2], bl[2];
                ldsm_x2(bh, ba);
                ldsm_x2(bl, ba + MATB);
#pragma unroll
                for (int mi = 0; mi < 4; mi++) mma16816(acc[mi][ni], ahi[mi], bh);
#pragma unroll
                for (int mi = 0; mi < 4; mi++) mma16816(acc[mi][ni], alo[mi], bh);
#pragma unroll
                for (int mi = 0; mi < 4; mi++) mma16816(acc[mi][ni], ahi[mi], bl);
            }
        }
        __syncthreads();
    }

#pragma unroll
    for (int mi = 0; mi < 4; mi++) {
        int r0 = rowBase + wm * 64 + mi * 16 + g;
        int r1 = r0 + 8;
#pragma unroll
        for (int ni = 0; ni < 4; ni++) {
            int col = colBase + wn * 32 + ni * 8 + tig * 2;
            bf16 h0, l0, h1, l1;
            bsplit(acc[mi][ni][0], h0, l0); bsplit(acc[mi][ni][1], h1, l1);
            *(__nv_bfloat162*)(Csp + (size_t)r0 * 5120 + col)        = __nv_bfloat162(h0, h1);
            *(__nv_bfloat162*)(Csp + (size_t)r0 * 5120 + 2560 + col) = __nv_bfloat162(l0, l1);
            bsplit(acc[mi][ni][2], h0, l0); bsplit(acc[mi][ni][3], h1, l1);
            *(__nv_bfloat162*)(Csp + (size_t)r1 * 5120 + col)        = __nv_bfloat162(h0, h1);
            *(__nv_bfloat162*)(Csp + (size_t)r1 * 5120 + 2560 + col) = __nv_bfloat162(l0, l1);
        }
    }
}

// ================= fused MLP (R11-proven), term-major =================
#define WGP 40
#define A_PL (128 * WGP * 2)
#define B_PL (256 * WGP * 2)
#define WSTAGE (2 * A_PL + 2 * B_PL)
#define HP 264
#define HPLANE (128 * HP * 2)
#define W2S0 (2 * HPLANE)
#define W2STG (2 * B_PL)
#define MLPSMEM (W2S0 + 2 * W2STG)

__global__ __launch_bounds__(256, 1)
void mlp_fused_kernel(const bf16* __restrict__ ln2sp,
                      const bf16* __restrict__ w1sp,
                      const bf16* __restrict__ w2sp,
                      const float* __restrict__ b1,
                      const float* __restrict__ b2,
                      const float* __restrict__ x2,
                      float* __restrict__ out) {
    extern __shared__ bf16 smem[];
    uint32_t sb = (uint32_t)__cvta_generic_to_shared(smem);

    int tid = threadIdx.x;
    int lane = tid & 31, warp = tid >> 5;
    int wm = warp & 1, wn = warp >> 1;
    int g = lane >> 2, tig = lane & 3;
    int lrow8 = lane & 7, l8 = (lane >> 3) & 1, l16 = (lane >> 4) & 1;
    int rowBase = blockIdx.x * 128;

    uint32_t aoff = (uint32_t)(((wm * 64 + lrow8 + 8 * l8) * WGP + 8 * l16) * 2);
    uint32_t boff = (uint32_t)(((wn * 64 + lrow8) * WGP + 8 * l8) * 2);
    uint32_t hoff = (uint32_t)(((wm * 64 + lrow8 + 8 * l8) * HP + 8 * l16) * 2);

    float acc[4][8][4] = {};

    auto load1 = [&](int c, int st) {
        const bf16* Ag = ln2sp + (size_t)rowBase * 512 + c * 32;
        const bf16* Bg = w1sp + c * 32;
        uint32_t base = sb + (uint32_t)st * WSTAGE;
#pragma unroll
        for (int i = 0; i < 2; i++) {
            int f = tid + i * 256;
            int r = f >> 2, q = f & 3;
            uint32_t so = (uint32_t)(r * WGP + q * 8) * 2;
            const bf16* ga = Ag + (size_t)r * 512 + q * 8;
            cpasync16(base + so,        ga);
            cpasync16(base + A_PL + so, ga + 256);
        }
#pragma unroll
        for (int i = 0; i < 4; i++) {
            int f = tid + i * 256;
            int r = f >> 2, q = f & 3;
            uint32_t so = (uint32_t)(r * WGP + q * 8) * 2;
            const bf16* gb = Bg + (size_t)r * 512 + q * 8;
            cpasync16(base + 2 * A_PL + so,        gb);
            cpasync16(base + 2 * A_PL + B_PL + so, gb + 256);
        }
        asm volatile("cp.async.commit_group;\n");
    };
    auto load2 = [&](int c, int st) {
        const bf16* Bg = w2sp + c * 32;
        uint32_t base = sb + W2S0 + (uint32_t)st * W2STG;
#pragma unroll
        for (int i = 0; i < 4; i++) {
            int f = tid + i * 256;
            int r = f >> 2, q = f & 3;
            uint32_t so = (uint32_t)(r * WGP + q * 8) * 2;
            const bf16* gb = Bg + (size_t)r * 512 + q * 8;
            cpasync16(base + so,        gb);
            cpasync16(base + B_PL + so, gb + 256);
        }
        asm volatile("cp.async.commit_group;\n");
    };

    // phase 1
    load1(0, 0);
    for (int c = 0; c < 8; c++) {
        if (c + 1 < 8) {
            load1(c + 1, (c + 1) & 1);
            asm volatile("cp.async.wait_group 1;\n");
        } else {
            asm volatile("cp.async.wait_group 0;\n");
        }
        __syncthreads();
        uint32_t stb = sb + (uint32_t)(c & 1) * WSTAGE;
#pragma unroll
        for (int ks = 0; ks < 2; ks++) {
            uint32_t kb2 = ks * 32;
            uint32_t ahi[4][4], alo[4][4];
#pragma unroll
            for (int mi = 0; mi < 4; mi++) {
                uint32_t a = stb + aoff + mi * (16 * WGP * 2) + kb2;
                ldsm_x4(ahi[mi], a);
                ldsm_x4(alo[mi], a + A_PL);
            }
#pragma unroll
            for (int ni = 0; ni < 8; ni++) {
                uint32_t ba = stb + 2 * A_PL + boff + ni * (8 * WGP * 2) + kb2;
                uint32_t bh[2], bl[2];
                ldsm_x2(bh, ba);
                ldsm_x2(bl, ba + B_PL);
#pragma unroll
                for (int mi = 0; mi < 4; mi++) mma16816(acc[mi][ni], ahi[mi], bh);
#pragma unroll
                for (int mi = 0; mi < 4; mi++) mma16816(acc[mi][ni], alo[mi], bh);
#pragma unroll
                for (int mi = 0; mi < 4; mi++) mma16816(acc[mi][ni], ahi[mi], bl);
            }
        }
        __syncthreads();
    }

    load2(0, 0);

    bf16* hhi = smem;
    bf16* hlo = smem + 128 * HP;
#pragma unroll
    for (int mi = 0; mi < 4; mi++) {
        int r0 = wm * 64 + mi * 16 + g;
        int r1 = r0 + 8;
#pragma unroll
        for (int ni = 0; ni < 8; ni++) {
            int col = wn * 64 + ni * 8 + tig * 2;
            float2 bv = *(const float2*)(b1 + col);
            float v0 = fmaxf(acc[mi][ni][0] + bv.x, 0.f);
            float v1 = fmaxf(acc[mi][ni][1] + bv.y, 0.f);
            float v2 = fmaxf(acc[mi][ni][2] + bv.x, 0.f);
            float v3 = fmaxf(acc[mi][ni][3] + bv.y, 0.f);
            bf16 h0, l0, h1, l1;
            bsplit(v0, h0, l0); bsplit(v1, h1, l1);
            *(__nv_bfloat162*)(hhi + r0 * HP + col) = __nv_bfloat162(h0, h1);
            *(__nv_bfloat162*)(hlo + r0 * HP + col) = __nv_bfloat162(l0, l1);
            bsplit(v2, h0, l0); bsplit(v3, h1, l1);
            *(__nv_bfloat162*)(hhi + r1 * HP + col) = __nv_bfloat162(h0, h1);
            *(__nv_bfloat162*)(hlo + r1 * HP + col) = __nv_bfloat162(l0, l1);
            acc[mi][ni][0] = 0.f; acc[mi][ni][1] = 0.f;
            acc[mi][ni][2] = 0.f; acc[mi][ni][3] = 0.f;
        }
    }
    __syncthreads();

    // phase 2
    for (int c = 0; c < 8; c++) {
        if (c + 1 < 8) {
            load2(c + 1, (c + 1) & 1);
            asm volatile("cp.async.wait_group 1;\n");
        } else {
            asm volatile("cp.async.wait_group 0;\n");
        }
        __syncthreads();
        uint32_t w2b = sb + W2S0 + (uint32_t)(c & 1) * W2STG;
#pragma unroll
        for (int ks = 0; ks < 2; ks++) {
            uint32_t kbyte = (uint32_t)((c * 32 + ks * 16) * 2);
            uint32_t kb2 = ks * 32;
            uint32_t ahi[4][4], alo[4][4];
#pragma unroll
            for (int mi = 0; mi < 4; mi++) {
                uint32_t a = sb + hoff + mi * (16 * HP * 2) + kbyte;
                ldsm_x4(ahi[mi], a);
                ldsm_x4(alo[mi], a + HPLANE);
            }
#pragma unroll
            for (int ni = 0; ni < 8; ni++) {
                uint32_t ba = w2b + boff + ni * (8 * WGP * 2) + kb2;
                uint32_t bh[2], bl[2];
                ldsm_x2(bh, ba);
                ldsm_x2(bl, ba + B_PL);
#pragma unroll
                for (int mi = 0; mi < 4; mi++) mma16816(acc[mi][ni], ahi[mi], bh);
#pragma unroll
                for (int mi = 0; mi < 4; mi++) mma16816(acc[mi][ni], alo[mi], bh);
#pragma unroll
                for (int mi = 0; mi < 4; mi++) mma16816(acc[mi][ni], ahi[mi], bl);
            }
        }
        __syncthreads();
    }

#pragma unroll
    for (int mi = 0; mi < 4; mi++) {
        int r0 = rowBase + wm * 64 + mi * 16 + g;
        int r1 = r0 + 8;
#pragma unroll
        for (int ni = 0; ni < 8; ni++) {
            int col = wn * 64 + ni * 8 + tig * 2;
            float2 bv = *(const float2*)(b2 + col);
            float2 e0 = *(const float2*)(x2 + (size_t)r0 * DD + col);
            float2 e1 = *(const float2*)(x2 + (size_t)r1 * DD + col);
            float2 v0 = make_float2(acc[mi][ni][0] + bv.x + e0.x,
                                    acc[mi][ni][1] + bv.y + e0.y);
            float2 v1 = make_float2(acc[mi][ni][2] + bv.x + e1.x,
                                    acc[mi][ni][3] + bv.y + e1.y);
            *(float2*)(out + (size_t)r0 * DD + col) = v0;
            *(float2*)(out + (size_t)r1 * DD + col) = v1;
        }
    }
}

// ================= tensor-core attention + fused head-mix (R11-proven) =================
#define TP 264
#define PP 72
#define TILE_E (64 * TP)
#define TEB (TILE_E * 2)
#define PPB (64 * PP * 2)
#define ATTN_SMEM_B (6 * TEB + 2 * PPB + 1024)

__global__ __launch_bounds__(256)
void attn_mma_kernel() {
    extern __shared__ bf16 asm_[];
    bf16* Ph = asm_ + 6 * TILE_E;
    bf16* Pl = Ph + 64 * PP;
    float* stmax = (float*)(Pl + 64 * PP);
    float* stsum = stmax + 128;
    uint32_t sbase = (uint32_t)__cvta_generic_to_shared(asm_);

    int tid = threadIdx.x;
    int lane = tid & 31, warp = tid >> 5;
    int g = lane >> 2, tig = lane & 3;
    int lrow8 = lane & 7, l8 = (lane >> 3) & 1, l16 = (lane >> 4) & 1;

    int u = blockIdx.x;
    bool gridmode = (u < 512);
    int b, fix;
    if (gridmode) { b = u >> 6; fix = u & 63; }
    else          { int u2 = u - 512; b = u2 >> 6; fix = u2 & 63; }
    size_t base; int stride;
    if (gridmode) { base = (size_t)b * 4096 + fix; stride = 64; }
    else          { base = (size_t)b * 4096 + (size_t)fix * 64; stride = 1; }
    int head0 = gridmode ? 0 : 4;

    auto load_piece = [&](int planeIdx, int colOff) {
        uint32_t sh = sbase + (uint32_t)planeIdx * TEB;
#pragma unroll
        for (int i = 0; i < 8; i++) {
            int f = i * 256 + tid;
            int r = f >> 5, q = f & 31;
            size_t token = base + (size_t)r * stride;
            const bf16* ga = g_qkvsp + token * 5120 + colOff + q * 8;
            uint32_t so = (uint32_t)(r * TP + q * 8) * 2;
            cpasync16(sh + so, ga);
            cpasync16(sh + TEB + so, ga + 2560);
        }
    };

    load_piece(2, 2048);
    load_piece(4, 2304);
    load_piece(0, head0 * 256);
    asm volatile("cp.async.commit_group;\n");
    asm volatile("cp.async.wait_group 0;\n");
    __syncthreads();

    int warpm = warp >> 1, warpn = warp & 1;
    int row0 = warpm * 16 + g, row1 = row0 + 8;

    uint32_t qoff = (uint32_t)(((warpm * 16 + lrow8 + 8 * l8) * TP + 8 * l16) * 2);
    uint32_t koff = (uint32_t)(((warpn * 32 + lrow8) * TP + 8 * l8) * 2);
    uint32_t poff = (uint32_t)(((warpm * 16 + lrow8 + 8 * l8) * PP + 8 * l16) * 2);
    uint32_t voff = (uint32_t)(((lrow8 + 8 * l8) * TP) * 2);
    uint32_t PB = sbase + 6 * TEB;
    uint32_t KB = sbase + 2 * TEB;
    uint32_t VB = sbase + 4 * TEB;

    float zacc[16][4] = {};

    for (int hl = 0; hl < 4; hl++) {
        int head = head0 + hl;

        float c[4][4] = {};
#pragma unroll 4
        for (int ks = 0; ks < 16; ks++) {
            uint32_t kb2 = ks * 32;
            uint32_t ahi[4], alo[4];
            ldsm_x4(ahi, sbase + qoff + kb2);
            ldsm_x4(alo, sbase + TEB + qoff + kb2);
            uint32_t bh[4][2], bl[4][2];
#pragma unroll
            for (int ni = 0; ni < 4; ni++) {
                uint32_t ba = KB + koff + ni * (8 * TP * 2) + kb2;
                ldsm_x2(bh[ni], ba);
                ldsm_x2(bl[ni], ba + TEB);
            }
#pragma unroll
            for (int ni = 0; ni < 4; ni++) mma16816(c[ni], ahi, bh[ni]);
#pragma unroll
            for (int ni = 0; ni < 4; ni++) mma16816(c[ni], alo, bh[ni]);
#pragma unroll
            for (int ni = 0; ni < 4; ni++) mma16816(c[ni], ahi, bl[ni]);
        }

        float m0 = -1e30f, m1 = -1e30f;
#pragma unroll
        for (int ni = 0; ni < 4; ni++) {
            m0 = fmaxf(m0, fmaxf(c[ni][0], c[ni][1]));
            m1 = fmaxf(m1, fmaxf(c[ni][2], c[ni][3]));
        }
        m0 = fmaxf(m0, __shfl_xor_sync(0xffffffffu, m0, 1));
        m0 = fmaxf(m0, __shfl_xor_sync(0xffffffffu, m0, 2));
        m1 = fmaxf(m1, __shfl_xor_sync(0xffffffffu, m1, 1));
        m1 = fmaxf(m1, __shfl_xor_sync(0xffffffffu, m1, 2));
        if (tig == 0) {
            stmax[row0 * 2 + warpn] = m0;
            stmax[row1 * 2 + warpn] = m1;
        }
        __syncthreads();
        m0 = fmaxf(stmax[row0 * 2], stmax[row0 * 2 + 1]);
        m1 = fmaxf(stmax[row1 * 2], stmax[row1 * 2 + 1]);
        float s0 = 0.f, s1 = 0.f;
#pragma unroll
        for (int ni = 0; ni < 4; ni++) {
            c[ni][0] = __expf(c[ni][0] - m0);
            c[ni][1] = __expf(c[ni][1] - m0);
            c[ni][2] = __expf(c[ni][2] - m1);
            c[ni][3] = __expf(c[ni][3] - m1);
            s0 += c[ni][0] + c[ni][1];
            s1 += c[ni][2] + c[ni][3];
        }
        s0 += __shfl_xor_sync(0xffffffffu, s0, 1);
        s0 += __shfl_xor_sync(0xffffffffu, s0, 2);
        s1 += __shfl_xor_sync(0xffffffffu, s1, 1);
        s1 += __shfl_xor_sync(0xffffffffu, s1, 2);
        if (tig == 0) {
            stsum[row0 * 2 + warpn] = s0;
            stsum[row1 * 2 + warpn] = s1;
        }
        __syncthreads();
        float inv0 = 1.0f / (stsum[row0 * 2] + stsum[row0 * 2 + 1]);
        float inv1 = 1.0f / (stsum[row1 * 2] + stsum[row1 * 2 + 1]);
#pragma unroll
        for (int ni = 0; ni < 4; ni++) {
            int cn = warpn * 32 + ni * 8 + 2 * tig;
            bf16 h0, l0, h1, l1;
            bsplit(c[ni][0] * inv0, h0, l0); bsplit(c[ni][1] * inv0, h1, l1);
            *(__nv_bfloat162*)(Ph + row0 * PP + cn) = __nv_bfloat162(h0, h1);
            *(__nv_bfloat162*)(Pl + row0 * PP + cn) = __nv_bfloat162(l0, l1);
            bsplit(c[ni][2] * inv1, h0, l0); bsplit(c[ni][3] * inv1, h1, l1);
            *(__nv_bfloat162*)(Ph + row1 * PP + cn) = __nv_bfloat162(h0, h1);
            *(__nv_bfloat162*)(Pl + row1 * PP + cn) = __nv_bfloat162(l0, l1);
        }
        __syncthreads();

        if (hl < 3) {
            load_piece(0, (head + 1) * 256);
            asm volatile("cp.async.commit_group;\n");
        }

        const float* sop = g_so + head * 256;
#pragma unroll
        for (int ks = 0; ks < 4; ks++) {
            uint32_t kb2 = ks * 32;
            uint32_t ph[4], pl[4];
            ldsm_x4(ph, PB + poff + kb2);
            ldsm_x4(pl, PB + PPB + poff + kb2);
            uint32_t vrow = VB + voff + (uint32_t)ks * (16 * TP * 2);
#pragma unroll
            for (int ni = 0; ni < 16; ni++) {
                uint32_t va = vrow + (uint32_t)((warpn * 128 + ni * 8) * 2);
                uint32_t bh[2], bl[2];
                ldsm_x2t(bh, va);
                ldsm_x2t(bl, va + TEB);
                float ot[4] = {};
                mma16816(ot, ph, bh);
                mma16816(ot, pl, bh);
                mma16816(ot, ph, bl);
                float2 sv = *(const float2*)(sop + warpn * 128 + ni * 8 + 2 * tig);
                zacc[ni][0] += ot[0] * sv.x; zacc[ni][1] += ot[1] * sv.y;
                zacc[ni][2] += ot[2] * sv.x; zacc[ni][3] += ot[3] * sv.y;
            }
        }

        if (hl < 3) asm volatile("cp.async.wait_group 0;\n");
        __syncthreads();
    }

    float* gz = gridmode ? g_z1 : g_z2;
    size_t tok0 = base + (size_t)row0 * stride;
    size_t tok1 = base + (size_t)row1 * stride;
#pragma unroll
    for (int ni = 0; ni < 16; ni++) {
        int col = warpn * 128 + ni * 8 + 2 * tig;
        *(float2*)(gz + tok0 * DD + col) = make_float2(zacc[ni][0], zacc[ni][1]);
        *(float2*)(gz + tok1 * DD + col) = make_float2(zacc[ni][2], zacc[ni][3]);
    }
}

// ---------- z1+z2 + unpermute + residual + LN2 -> split bf16 ----------
__global__ void zred_ln2_kernel(const float* __restrict__ x,
                                const float* __restrict__ gamma,
                                const float* __restrict__ beta,
                                float* __restrict__ x2) {
    int gw   = (blockIdx.x * blockDim.x + threadIdx.x) >> 5;
    int lane = threadIdx.x & 31;

    int b = gw >> 12, m = (gw >> 6) & 63, n = gw & 63;
    int hh = ((n >> 3) << 3) | (m >> 3);
    int ww = ((n & 7) << 3) | (m & 7);
    size_t orow = ((size_t)b << 12) | (unsigned)((hh << 6) | ww);

    const float* z1 = g_z1 + (size_t)gw * DD;
    const float* z2 = g_z2 + (size_t)gw * DD;
    float4 a0 = ((const float4*)z1)[lane];
    float4 a1 = ((const float4*)z1)[lane + 32];
    float4 b0v = ((const float4*)z2)[lane];
    float4 b1v = ((const float4*)z2)[lane + 32];
    const float* xr = x + orow * DD;
    float4 x0 = ((const float4*)xr)[lane];
    float4 x1 = ((const float4*)xr)[lane + 32];
    float4 v0 = make_float4(x0.x + a0.x + b0v.x, x0.y + a0.y + b0v.y,
                            x0.z + a0.z + b0v.z, x0.w + a0.w + b0v.w);
    float4 v1 = make_float4(x1.x + a1.x + b1v.x, x1.y + a1.y + b1v.y,
                            x1.z + a1.z + b1v.z, x1.w + a1.w + b1v.w);

    ((float4*)(x2 + orow * DD))[lane]      = v0;
    ((float4*)(x2 + orow * DD))[lane + 32] = v1;

    float s  = v0.x + v0.y + v0.z + v0.w + v1.x + v1.y + v1.z + v1.w;
    float sq = v0.x*v0.x + v0.y*v0.y + v0.z*v0.z + v0.w*v0.w
             + v1.x*v1.x + v1.y*v1.y + v1.z*v1.z + v1.w*v1.w;
#pragma unroll
    for (int o = 16; o > 0; o >>= 1) {
        s  += __shfl_xor_sync(0xffffffffu, s,  o);
        sq += __shfl_xor_sync(0xffffffffu, sq, o);
    }
    float mean = s * (1.0f / 256.0f);
    float var  = sq * (1.0f / 256.0f) - mean * mean;
    float rstd = rsqrtf(var + 1e-5f);

    float4 g0 = ((const float4*)gamma)[lane];
    float4 g1 = ((const float4*)gamma)[lane + 32];
    float4 bb0 = ((const float4*)beta)[lane];
    float4 bb1 = ((const float4*)beta)[lane + 32];
    float4 o0, o1;
    o0.x = (v0.x - mean) * rstd * g0.x + bb0.x;
    o0.y = (v0.y - mean) * rstd * g0.y + bb0.y;
    o0.z = (v0.z - mean) * rstd * g0.z + bb0.z;
    o0.w = (v0.w - mean) * rstd * g0.w + bb0.w;
    o1.x = (v1.x - mean) * rstd * g1.x + bb1.x;
    o1.y = (v1.y - mean) * rstd * g1.y + bb1.y;
    o1.z = (v1.z - mean) * rstd * g1.z + bb1.z;
    o1.w = (v1.w - mean) * rstd * g1.w + bb1.w;
    store_split8(g_ln2sp + orow * 512, lane * 4, o0, o1);
}

// ---------------- launch ----------------
extern "C" void kernel_launch(void* const* d_in, const int* in_sizes, int n_in,
                              void* d_out, int out_size) {
    const float* x    = (const float*)d_in[0];
    const float* ln1w = (const float*)d_in[1];
    const float* ln1b = (const float*)d_in[2];
    const float* qw   = (const float*)d_in[3];
    const float* kw   = (const float*)d_in[4];
    const float* vw   = (const float*)d_in[5];
    const float* ow   = (const float*)d_in[6];
    const float* ln2w = (const float*)d_in[7];
    const float* ln2b = (const float*)d_in[8];
    const float* w1   = (const float*)d_in[9];
    const float* b1   = (const float*)d_in[10];
    const float* w2   = (const float*)d_in[11];
    const float* b2   = (const float*)d_in[12];
    float* out = (float*)d_out;

    bf16 *p_asp, *p_wsp, *p_w1sp, *p_w2sp, *p_ln2sp, *p_qkvsp;
    float *p_x2;
    cudaGetSymbolAddress((void**)&p_asp,   g_asp);
    cudaGetSymbolAddress((void**)&p_wsp,   g_wsp);
    cudaGetSymbolAddress((void**)&p_w1sp,  g_w1sp);
    cudaGetSymbolAddress((void**)&p_w2sp,  g_w2sp);
    cudaGetSymbolAddress((void**)&p_ln2sp, g_ln2sp);
    cudaGetSymbolAddress((void**)&p_qkvsp, g_qkvsp);
    cudaGetSymbolAddress((void**)&p_x2,    g_x2);

    cudaFuncSetAttribute(attn_mma_kernel, cudaFuncAttributeMaxDynamicSharedMemorySize,
                         ATTN_SMEM_B);
    cudaFuncSetAttribute(qkv_gemm_kernel, cudaFuncAttributeMaxDynamicSharedMemorySize, GSMEM);
    cudaFuncSetAttribute(mlp_fused_kernel, cudaFuncAttributeMaxDynamicSharedMemorySize, MLPSMEM);

    prep_wqkv_kernel<<<QKVC, 256>>>(qw, kw, vw);                       // 1
    ln1_kernel<<<NTOK / 8, 256>>>(x, ln1w, ln1b);                      // 2
    prep_wt_kernel<<<256, 256>>>(w1, p_w1sp);                          // 3
    qkv_gemm_kernel<<<dim3(QKVC / 128, NTOK / 128), 256, GSMEM>>>(     // 4
        p_asp, p_wsp, p_qkvsp);
    prep_so_kernel<<<256, 256>>>(ow);                                  // 5
    prep_wt_kernel<<<256, 256>>>(w2, p_w2sp);                          // 6
    attn_mma_kernel<<<1024, 256, ATTN_SMEM_B>>>();                     // 7
    zred_ln2_kernel<<<NTOK / 8, 256>>>(x, ln2w, ln2b, p_x2);           // 8
    mlp_fused_kernel<<<NTOK / 128, 256, MLPSMEM>>>(                    // 9
        p_ln2sp, p_w1sp, p_w2sp, b1, b2, p_x2, out);
}

// round 16
// speedup vs baseline: 1.7387x; 1.0033x over previous
#include <cuda_runtime.h>
#include <cuda_bf16.h>
#include <cstdint>
#include <cstddef>

typedef __nv_bfloat16 bf16;

// ---------------- problem constants ----------------
#define NTOK     32768
#define DD       256
#define QKVC     2560

// ---------------- static scratch ----------------
__device__ bf16 g_asp  [(size_t)NTOK * 512];
__device__ bf16 g_wsp  [(size_t)QKVC * 512];
__device__ bf16 g_w1sp [(size_t)DD * 512];
__device__ bf16 g_w2sp [(size_t)DD * 512];
__device__ bf16 g_qkvsp[(size_t)NTOK * 5120];
__device__ float g_z1  [(size_t)NTOK * DD];
__device__ float g_z2  [(size_t)NTOK * DD];
__device__ float g_so  [2048];
__device__ float g_x2  [(size_t)NTOK * DD];

// ---------------- helpers ----------------
__device__ __forceinline__ void bsplit(float v, bf16& h, bf16& l) {
    h = __float2bfloat16_rn(v);
    l = __float2bfloat16_rn(v - __bfloat162float(h));
}
__device__ __forceinline__ void cpasync16(uint32_t s, const void* g) {
    asm volatile("cp.async.cg.shared.global [%0], [%1], 16;\n" :: "r"(s), "l"(g));
}
__device__ __forceinline__ void mma16816(float* c, const uint32_t* a, const uint32_t* b) {
    asm volatile(
        "mma.sync.aligned.m16n8k16.row.col.f32.bf16.bf16.f32 "
        "{%0,%1,%2,%3},{%4,%5,%6,%7},{%8,%9},{%0,%1,%2,%3};\n"
        : "+f"(c[0]), "+f"(c[1]), "+f"(c[2]), "+f"(c[3])
        : "r"(a[0]), "r"(a[1]), "r"(a[2]), "r"(a[3]), "r"(b[0]), "r"(b[1]));
}
__device__ __forceinline__ void ldsm_x4(uint32_t* r, uint32_t a) {
    asm volatile("ldmatrix.sync.aligned.m8n8.x4.shared.b16 {%0,%1,%2,%3}, [%4];"
        : "=r"(r[0]), "=r"(r[1]), "=r"(r[2]), "=r"(r[3]) : "r"(a));
}
__device__ __forceinline__ void ldsm_x2(uint32_t* r, uint32_t a) {
    asm volatile("ldmatrix.sync.aligned.m8n8.x2.shared.b16 {%0,%1}, [%2];"
        : "=r"(r[0]), "=r"(r[1]) : "r"(a));
}
__device__ __forceinline__ void ldsm_x2t(uint32_t* r, uint32_t a) {
    asm volatile("ldmatrix.sync.aligned.m8n8.x2.trans.shared.b16 {%0,%1}, [%2];"
        : "=r"(r[0]), "=r"(r[1]) : "r"(a));
}
__device__ __forceinline__ void store_split8(bf16* rowp, int col, float4 v0, float4 v1) {
    bf16 h[8], l[8];
    bsplit(v0.x, h[0], l[0]); bsplit(v0.y, h[1], l[1]);
    bsplit(v0.z, h[2], l[2]); bsplit(v0.w, h[3], l[3]);
    bsplit(v1.x, h[4], l[4]); bsplit(v1.y, h[5], l[5]);
    bsplit(v1.z, h[6], l[6]); bsplit(v1.w, h[7], l[7]);
#pragma unroll
    for (int i = 0; i < 4; i++) {
        rowp[col + i]             = h[i];
        rowp[col + 128 + i]       = h[4 + i];
        rowp[256 + col + i]       = l[i];
        rowp[256 + col + 128 + i] = l[4 + i];
    }
}

// ---------------- merged weight prep (wqkv | w1 | w2 | so) ----------------
__global__ void prep_all_kernel(const float* __restrict__ q,
                                const float* __restrict__ k,
                                const float* __restrict__ v,
                                const float* __restrict__ w1,
                                const float* __restrict__ w2,
                                const float* __restrict__ o,
                                bf16* __restrict__ w1sp,
                                bf16* __restrict__ w2sp) {
    int bx = blockIdx.x;
    int tid = threadIdx.x;
    if (bx < 2560) {
        int idx = bx * 256 + tid;
        int d = idx & 255, j = idx >> 8;
        float val;
        if (j < 2048) { int h = j >> 8, kk = j & 255; val = q[((size_t)(h * 256 + d)) * 256 + kk]; }
        else if (j < 2304) val = k[(size_t)d * 256 + (j - 2048)];
        else               val = v[(size_t)d * 256 + (j - 2304)];
        bf16 h16, l16; bsplit(val, h16, l16);
        g_wsp[(size_t)j * 512 + d]       = h16;
        g_wsp[(size_t)j * 512 + 256 + d] = l16;
    } else if (bx < 3072) {
        int bb = bx - 2560;
        const float* src = (bb < 256) ? w1 : w2;
        bf16* dst = (bb < 256) ? w1sp : w2sp;
        int idx = (bb & 255) * 256 + tid;
        int d = idx & 255, j = idx >> 8;
        float val = src[(size_t)d * 256 + j];
        bf16 h16, l16; bsplit(val, h16, l16);
        dst[(size_t)j * 512 + d]       = h16;
        dst[(size_t)j * 512 + 256 + d] = l16;
    } else {
        int bxx = bx - 3072;
        int row  = (bxx * 256 + tid) >> 5;
        int lane = tid & 31;
        const float* rp = o + (size_t)row * 256;
        float4 a = ((const float4*)rp)[lane];
        float4 b = ((const float4*)rp)[lane + 32];
        float s = a.x + a.y + a.z + a.w + b.x + b.y + b.z + b.w;
#pragma unroll
        for (int off = 16; off > 0; off >>= 1) s += __shfl_xor_sync(0xffffffffu, s, off);
        if (lane == 0) g_so[row] = s;
    }
}

// ---------------- LN1 + block permute -> split bf16 ----------------
__global__ void ln1_kernel(const float* __restrict__ in,
                           const float* __restrict__ gamma,
                           const float* __restrict__ beta) {
    int gwarp = (blockIdx.x * blockDim.x + threadIdx.x) >> 5;
    int lane  = threadIdx.x & 31;
    const float* row = in + (size_t)gwarp * DD;
    float4 v0 = ((const float4*)row)[lane];
    float4 v1 = ((const float4*)row)[lane + 32];
    float s  = v0.x + v0.y + v0.z + v0.w + v1.x + v1.y + v1.z + v1.w;
    float sq = v0.x*v0.x + v0.y*v0.y + v0.z*v0.z + v0.w*v0.w
             + v1.x*v1.x + v1.y*v1.y + v1.z*v1.z + v1.w*v1.w;
#pragma unroll
    for (int o = 16; o > 0; o >>= 1) {
        s  += __shfl_xor_sync(0xffffffffu, s,  o);
        sq += __shfl_xor_sync(0xffffffffu, sq, o);
    }
    float mean = s * (1.0f / 256.0f);
    float var  = sq * (1.0f / 256.0f) - mean * mean;
    float rstd = rsqrtf(var + 1e-5f);

    int b = gwarp >> 12, pos = gwarp & 4095;
    int h = pos >> 6, w = pos & 63;
    int m = ((h & 7) << 3) | (w & 7);
    int n = ((h >> 3) << 3) | (w >> 3);
    size_t orow = ((size_t)b << 12) | (unsigned)((m << 6) | n);

    float4 g0 = ((const float4*)gamma)[lane];
    float4 g1 = ((const float4*)gamma)[lane + 32];
    float4 b0 = ((const float4*)beta)[lane];
    float4 b1 = ((const float4*)beta)[lane + 32];
    float4 o0, o1;
    o0.x = (v0.x - mean) * rstd * g0.x + b0.x;
    o0.y = (v0.y - mean) * rstd * g0.y + b0.y;
    o0.z = (v0.z - mean) * rstd * g0.z + b0.z;
    o0.w = (v0.w - mean) * rstd * g0.w + b0.w;
    o1.x = (v1.x - mean) * rstd * g1.x + b1.x;
    o1.y = (v1.y - mean) * rstd * g1.y + b1.y;
    o1.z = (v1.z - mean) * rstd * g1.z + b1.z;
    o1.w = (v1.w - mean) * rstd * g1.w + b1.w;
    store_split8(g_asp + orow * 512, lane * 4, o0, o1);
}

// ================= QKV GEMM: 128x128 tile, term-major 3-split (R14-proven) =================
#define GP 40
#define MATB (128 * GP * 2)
#define STAGEB (4 * MATB)
#define GSMEM (2 * STAGEB)

__global__ __launch_bounds__(256, 2)
void qkv_gemm_kernel(const bf16* __restrict__ Asp,
                     const bf16* __restrict__ Bsp,
                     bf16* __restrict__ Csp) {
    extern __shared__ bf16 smem[];
    uint32_t sb = (uint32_t)__cvta_generic_to_shared(smem);

    int tid = threadIdx.x;
    int lane = tid & 31, warp = tid >> 5;
    int wm = warp & 1, wn = warp >> 1;
    int g = lane >> 2, tig = lane & 3;
    int lrow8 = lane & 7, l8 = (lane >> 3) & 1, l16 = (lane >> 4) & 1;
    int rowBase = blockIdx.y * 128;
    int colBase = blockIdx.x * 128;

    uint32_t aoff = (uint32_t)(((wm * 64 + lrow8 + 8 * l8) * GP + 8 * l16) * 2);
    uint32_t boff = (uint32_t)(((wn * 32 + lrow8) * GP + 8 * l8) * 2);

    float acc[4][4][4] = {};

    auto load_chunk = [&](int c, int st) {
        const bf16* Ag = Asp + (size_t)rowBase * 512 + c * 32;
        const bf16* Bg = Bsp + (size_t)colBase * 512 + c * 32;
        uint32_t base = sb + (uint32_t)st * STAGEB;
#pragma unroll
        for (int i = 0; i < 2; i++) {
            int f = tid + i * 256;
            int r = f >> 2, q = f & 3;
            uint32_t so = (uint32_t)(r * GP + q * 8) * 2;
            const bf16* ga = Ag + (size_t)r * 512 + q * 8;
            const bf16* gb = Bg + (size_t)r * 512 + q * 8;
            cpasync16(base + so,            ga);
            cpasync16(base + MATB + so,     ga + 256);
            cpasync16(base + 2 * MATB + so, gb);
            cpasync16(base + 3 * MATB + so, gb + 256);
        }
        asm volatile("cp.async.commit_group;\n");
    };

    load_chunk(0, 0);
    const int NCH = 8;
    for (int c = 0; c < NCH; c++) {
        if (c + 1 < NCH) {
            load_chunk(c + 1, (c + 1) & 1);
            asm volatile("cp.async.wait_group 1;\n");
        } else {
            asm volatile("cp.async.wait_group 0;\n");
        }
        __syncthreads();

        uint32_t stb = sb + (uint32_t)(c & 1) * STAGEB;
#pragma unroll
        for (int ks = 0; ks < 2; ks++) {
            uint32_t kb2 = ks * 32;
            uint32_t ahi[4][4], alo[4][4];
#pragma unroll
            for (int mi = 0; mi < 4; mi++) {
                uint32_t a = stb + aoff + mi * (16 * GP * 2) + kb2;
                ldsm_x4(ahi[mi], a);
                ldsm_x4(alo[mi], a + MATB);
            }
#pragma unroll
            for (int ni = 0; ni < 4; ni++) {
                uint32_t ba = stb + 2 * MATB + boff + ni * (8 * GP * 2) + kb2;
                uint32_t bh[2], bl[2];
                ldsm_x2(bh, ba);
                ldsm_x2(bl, ba + MATB);
#pragma unroll
                for (int mi = 0; mi < 4; mi++) mma16816(acc[mi][ni], ahi[mi], bh);
#pragma unroll
                for (int mi = 0; mi < 4; mi++) mma16816(acc[mi][ni], alo[mi], bh);
#pragma unroll
                for (int mi = 0; mi < 4; mi++) mma16816(acc[mi][ni], ahi[mi], bl);
            }
        }
        __syncthreads();
    }

#pragma unroll
    for (int mi = 0; mi < 4; mi++) {
        int r0 = rowBase + wm * 64 + mi * 16 + g;
        int r1 = r0 + 8;
#pragma unroll
        for (int ni = 0; ni < 4; ni++) {
            int col = colBase + wn * 32 + ni * 8 + tig * 2;
            bf16 h0, l0, h1, l1;
            bsplit(acc[mi][ni][0], h0, l0); bsplit(acc[mi][ni][1], h1, l1);
            *(__nv_bfloat162*)(Csp + (size_t)r0 * 5120 + col)        = __nv_bfloat162(h0, h1);
            *(__nv_bfloat162*)(Csp + (size_t)r0 * 5120 + 2560 + col) = __nv_bfloat162(l0, l1);
            bsplit(acc[mi][ni][2], h0, l0); bsplit(acc[mi][ni][3], h1, l1);
            *(__nv_bfloat162*)(Csp + (size_t)r1 * 5120 + col)        = __nv_bfloat162(h0, h1);
            *(__nv_bfloat162*)(Csp + (size_t)r1 * 5120 + 2560 + col) = __nv_bfloat162(l0, l1);
        }
    }
}

// ================= fused zred+LN2+MLP =================
#define WGP 40
#define B_PL (256 * WGP * 2)
#define AP2 520
#define HP 264
#define HPLANE (128 * HP * 2)
#define STG0 (2 * HPLANE)
#define BSTG (2 * B_PL)
#define MLP2SMEM (STG0 + 2 * BSTG)

__global__ __launch_bounds__(256, 1)
void mlp_fused_kernel(const float* __restrict__ x,
                      const float* __restrict__ gamma,
                      const float* __restrict__ beta,
                      const bf16* __restrict__ w1sp,
                      const bf16* __restrict__ w2sp,
                      const float* __restrict__ b1,
                      const float* __restrict__ b2,
                      float* __restrict__ x2,
                      float* __restrict__ out) {
    extern __shared__ bf16 smem[];
    uint32_t sb = (uint32_t)__cvta_generic_to_shared(smem);

    int tid = threadIdx.x;
    int lane = tid & 31, warp = tid >> 5;
    int wm = warp & 1, wn = warp >> 1;
    int g = lane >> 2, tig = lane & 3;
    int lrow8 = lane & 7, l8 = (lane >> 3) & 1, l16 = (lane >> 4) & 1;
    int rowBase = blockIdx.x * 128;

    uint32_t aoff2 = (uint32_t)(((wm * 64 + lrow8 + 8 * l8) * AP2 + 8 * l16) * 2);
    uint32_t boff  = (uint32_t)(((wn * 64 + lrow8) * WGP + 8 * l8) * 2);
    uint32_t hoff  = (uint32_t)(((wm * 64 + lrow8 + 8 * l8) * HP + 8 * l16) * 2);

    auto loadB = [&](const bf16* Bg0, int c, int st) {
        const bf16* Bg = Bg0 + c * 32;
        uint32_t base = sb + STG0 + (uint32_t)st * BSTG;
#pragma unroll
        for (int i = 0; i < 4; i++) {
            int f = tid + i * 256;
            int r = f >> 2, q = f & 3;
            uint32_t so = (uint32_t)(r * WGP + q * 8) * 2;
            const bf16* gb = Bg + (size_t)r * 512 + q * 8;
            cpasync16(base + so,        gb);
            cpasync16(base + B_PL + so, gb + 256);
        }
        asm volatile("cp.async.commit_group;\n");
    };

    loadB(w1sp, 0, 0);

    // ---- prologue: zred + LN2 -> smem A ----
    // orig row (hh,ww) reads blocked token via FORWARD map:
    //   mm = ((hh&7)<<3)|(ww&7), nn = ((hh>>3)<<3)|(ww>>3)   [bugfix from R15]
    {
        bf16* Asm = smem;
#pragma unroll 1
        for (int rr = 0; rr < 16; rr++) {
            int lr = warp * 16 + rr;
            int orow_ = rowBase + lr;
            int bb = orow_ >> 12, hh = (orow_ >> 6) & 63, ww = orow_ & 63;
            int mm = ((hh & 7) << 3) | (ww & 7);
            int nn = ((hh >> 3) << 3) | (ww >> 3);
            size_t gw = ((size_t)bb << 12) | (unsigned)((mm << 6) | nn);

            const float* z1p = g_z1 + gw * DD;
            const float* z2p = g_z2 + gw * DD;
            const float* xp  = x + (size_t)orow_ * DD;
            float4 a0 = ((const float4*)z1p)[lane];
            float4 a1 = ((const float4*)z1p)[lane + 32];
            float4 c0 = ((const float4*)z2p)[lane];
            float4 c1 = ((const float4*)z2p)[lane + 32];
            float4 x0 = ((const float4*)xp)[lane];
            float4 x1 = ((const float4*)xp)[lane + 32];
            float4 v0 = make_float4(x0.x + a0.x + c0.x, x0.y + a0.y + c0.y,
                                    x0.z + a0.z + c0.z, x0.w + a0.w + c0.w);
            float4 v1 = make_float4(x1.x + a1.x + c1.x, x1.y + a1.y + c1.y,
                                    x1.z + a1.z + c1.z, x1.w + a1.w + c1.w);

            ((float4*)(x2 + (size_t)orow_ * DD))[lane]      = v0;
            ((float4*)(x2 + (size_t)orow_ * DD))[lane + 32] = v1;

            float s  = v0.x + v0.y + v0.z + v0.w + v1.x + v1.y + v1.z + v1.w;
            float sq = v0.x*v0.x + v0.y*v0.y + v0.z*v0.z + v0.w*v0.w
                     + v1.x*v1.x + v1.y*v1.y + v1.z*v1.z + v1.w*v1.w;
#pragma unroll
            for (int o = 16; o > 0; o >>= 1) {
                s  += __shfl_xor_sync(0xffffffffu, s,  o);
                sq += __shfl_xor_sync(0xffffffffu, sq, o);
            }
            float mean = s * (1.0f / 256.0f);
            float var  = sq * (1.0f / 256.0f) - mean * mean;
            float rstd = rsqrtf(var + 1e-5f);

            float4 g0 = ((const float4*)gamma)[lane];
            float4 g1 = ((const float4*)gamma)[lane + 32];
            float4 bb0 = ((const float4*)beta)[lane];
            float4 bb1 = ((const float4*)beta)[lane + 32];
            float4 o0, o1;
            o0.x = (v0.x - mean) * rstd * g0.x + bb0.x;
            o0.y = (v0.y - mean) * rstd * g0.y + bb0.y;
            o0.z = (v0.z - mean) * rstd * g0.z + bb0.z;
            o0.w = (v0.w - mean) * rstd * g0.w + bb0.w;
            o1.x = (v1.x - mean) * rstd * g1.x + bb1.x;
            o1.y = (v1.y - mean) * rstd * g1.y + bb1.y;
            o1.z = (v1.z - mean) * rstd * g1.z + bb1.z;
            o1.w = (v1.w - mean) * rstd * g1.w + bb1.w;
            store_split8(Asm + (size_t)lr * AP2, lane * 4, o0, o1);
        }
    }
    __syncthreads();

    float acc[4][8][4] = {};

    // ---- phase 1: h = relu(A @ w1 + b1), A resident in smem ----
    for (int c = 0; c < 8; c++) {
        if (c + 1 < 8) {
            loadB(w1sp, c + 1, (c + 1) & 1);
            asm volatile("cp.async.wait_group 1;\n");
        } else {
            asm volatile("cp.async.wait_group 0;\n");
        }
        __syncthreads();
        uint32_t stg = sb + STG0 + (uint32_t)(c & 1) * BSTG;
#pragma unroll
        for (int ks = 0; ks < 2; ks++) {
            uint32_t kbyte = (uint32_t)((c * 32 + ks * 16) * 2);
            uint32_t kb2 = ks * 32;
            uint32_t ahi[4][4], alo[4][4];
#pragma unroll
            for (int mi = 0; mi < 4; mi++) {
                uint32_t a = sb + aoff2 + mi * (16 * AP2 * 2) + kbyte;
                ldsm_x4(ahi[mi], a);
                ldsm_x4(alo[mi], a + 512);
            }
#pragma unroll
            for (int ni = 0; ni < 8; ni++) {
                uint32_t ba = stg + boff + ni * (8 * WGP * 2) + kb2;
                uint32_t bh[2], bl[2];
                ldsm_x2(bh, ba);
                ldsm_x2(bl, ba + B_PL);
#pragma unroll
                for (int mi = 0; mi < 4; mi++) mma16816(acc[mi][ni], ahi[mi], bh);
#pragma unroll
                for (int mi = 0; mi < 4; mi++) mma16816(acc[mi][ni], alo[mi], bh);
#pragma unroll
                for (int mi = 0; mi < 4; mi++) mma16816(acc[mi][ni], ahi[mi], bl);
            }
        }
        __syncthreads();
    }

    loadB(w2sp, 0, 0);

    bf16* hhi = smem;
    bf16* hlo = smem + 128 * HP;
#pragma unroll
    for (int mi = 0; mi < 4; mi++) {
        int r0 = wm * 64 + mi * 16 + g;
        int r1 = r0 + 8;
#pragma unroll
        for (int ni = 0; ni < 8; ni++) {
            int col = wn * 64 + ni * 8 + tig * 2;
            float2 bv = *(const float2*)(b1 + col);
            float v0 = fmaxf(acc[mi][ni][0] + bv.x, 0.f);
            float v1 = fmaxf(acc[mi][ni][1] + bv.y, 0.f);
            float v2 = fmaxf(acc[mi][ni][2] + bv.x, 0.f);
            float v3 = fmaxf(acc[mi][ni][3] + bv.y, 0.f);
            bf16 h0, l0, h1, l1;
            bsplit(v0, h0, l0); bsplit(v1, h1, l1);
            *(__nv_bfloat162*)(hhi + r0 * HP + col) = __nv_bfloat162(h0, h1);
            *(__nv_bfloat162*)(hlo + r0 * HP + col) = __nv_bfloat162(l0, l1);
            bsplit(v2, h0, l0); bsplit(v3, h1, l1);
            *(__nv_bfloat162*)(hhi + r1 * HP + col) = __nv_bfloat162(h0, h1);
            *(__nv_bfloat162*)(hlo + r1 * HP + col) = __nv_bfloat162(l0, l1);
            acc[mi][ni][0] = 0.f; acc[mi][ni][1] = 0.f;
            acc[mi][ni][2] = 0.f; acc[mi][ni][3] = 0.f;
        }
    }
    __syncthreads();

    // ---- phase 2: out = h @ w2 + b2 + x2 ----
    for (int c = 0; c < 8; c++) {
        if (c + 1 < 8) {
            loadB(w2sp, c + 1, (c + 1) & 1);
            asm volatile("cp.async.wait_group 1;\n");
        } else {
            asm volatile("cp.async.wait_group 0;\n");
        }
        __syncthreads();
        uint32_t stg = sb + STG0 + (uint32_t)(c & 1) * BSTG;
#pragma unroll
        for (int ks = 0; ks < 2; ks++) {
            uint32_t kbyte = (uint32_t)((c * 32 + ks * 16) * 2);
            uint32_t kb2 = ks * 32;
            uint32_t ahi[4][4], alo[4][4];
#pragma unroll
            for (int mi = 0; mi < 4; mi++) {
                uint32_t a = sb + hoff + mi * (16 * HP * 2) + kbyte;
                ldsm_x4(ahi[mi], a);
                ldsm_x4(alo[mi], a + HPLANE);
            }
#pragma unroll
            for (int ni = 0; ni < 8; ni++) {
                uint32_t ba = stg + boff + ni * (8 * WGP * 2) + kb2;
                uint32_t bh[2], bl[2];
                ldsm_x2(bh, ba);
                ldsm_x2(bl, ba + B_PL);
#pragma unroll
                for (int mi = 0; mi < 4; mi++) mma16816(acc[mi][ni], ahi[mi], bh);
#pragma unroll
                for (int mi = 0; mi < 4; mi++) mma16816(acc[mi][ni], alo[mi], bh);
#pragma unroll
                for (int mi = 0; mi < 4; mi++) mma16816(acc[mi][ni], ahi[mi], bl);
            }
        }
        __syncthreads();
    }

#pragma unroll
    for (int mi = 0; mi < 4; mi++) {
        int r0 = rowBase + wm * 64 + mi * 16 + g;
        int r1 = r0 + 8;
#pragma unroll
        for (int ni = 0; ni < 8; ni++) {
            int col = wn * 64 + ni * 8 + tig * 2;
            float2 bv = *(const float2*)(b2 + col);
            float2 e0 = *(const float2*)(x2 + (size_t)r0 * DD + col);
            float2 e1 = *(const float2*)(x2 + (size_t)r1 * DD + col);
            float2 v0 = make_float2(acc[mi][ni][0] + bv.x + e0.x,
                                    acc[mi][ni][1] + bv.y + e0.y);
            float2 v1 = make_float2(acc[mi][ni][2] + bv.x + e1.x,
                                    acc[mi][ni][3] + bv.y + e1.y);
            *(float2*)(out + (size_t)r0 * DD + col) = v0;
            *(float2*)(out + (size_t)r1 * DD + col) = v1;
        }
    }
}

// ================= tensor-core attention + fused head-mix (R14-proven) =================
#define TP 264
#define PP 72
#define TILE_E (64 * TP)
#define TEB (TILE_E * 2)
#define PPB (64 * PP * 2)
#define ATTN_SMEM_B (6 * TEB + 2 * PPB + 1024)

__global__ __launch_bounds__(256)
void attn_mma_kernel() {
    extern __shared__ bf16 asm_[];
    bf16* Ph = asm_ + 6 * TILE_E;
    bf16* Pl = Ph + 64 * PP;
    float* stmax = (float*)(Pl + 64 * PP);
    float* stsum = stmax + 128;
    uint32_t sbase = (uint32_t)__cvta_generic_to_shared(asm_);

    int tid = threadIdx.x;
    int lane = tid & 31, warp = tid >> 5;
    int g = lane >> 2, tig = lane & 3;
    int lrow8 = lane & 7, l8 = (lane >> 3) & 1, l16 = (lane >> 4) & 1;

    int u = blockIdx.x;
    bool gridmode = (u < 512);
    int b, fix;
    if (gridmode) { b = u >> 6; fix = u & 63; }
    else          { int u2 = u - 512; b = u2 >> 6; fix = u2 & 63; }
    size_t base; int stride;
    if (gridmode) { base = (size_t)b * 4096 + fix; stride = 64; }
    else          { base = (size_t)b * 4096 + (size_t)fix * 64; stride = 1; }
    int head0 = gridmode ? 0 : 4;

    auto load_piece = [&](int planeIdx, int colOff) {
        uint32_t sh = sbase + (uint32_t)planeIdx * TEB;
#pragma unroll
        for (int i = 0; i < 8; i++) {
            int f = i * 256 + tid;
            int r = f >> 5, q = f & 31;
            size_t token = base + (size_t)r * stride;
            const bf16* ga = g_qkvsp + token * 5120 + colOff + q * 8;
            uint32_t so = (uint32_t)(r * TP + q * 8) * 2;
            cpasync16(sh + so, ga);
            cpasync16(sh + TEB + so, ga + 2560);
        }
    };

    load_piece(2, 2048);
    load_piece(4, 2304);
    load_piece(0, head0 * 256);
    asm volatile("cp.async.commit_group;\n");
    asm volatile("cp.async.wait_group 0;\n");
    __syncthreads();

    int warpm = warp >> 1, warpn = warp & 1;
    int row0 = warpm * 16 + g, row1 = row0 + 8;

    uint32_t qoff = (uint32_t)(((warpm * 16 + lrow8 + 8 * l8) * TP + 8 * l16) * 2);
    uint32_t koff = (uint32_t)(((warpn * 32 + lrow8) * TP + 8 * l8) * 2);
    uint32_t poff = (uint32_t)(((warpm * 16 + lrow8 + 8 * l8) * PP + 8 * l16) * 2);
    uint32_t voff = (uint32_t)(((lrow8 + 8 * l8) * TP) * 2);
    uint32_t PB = sbase + 6 * TEB;
    uint32_t KB = sbase + 2 * TEB;
    uint32_t VB = sbase + 4 * TEB;

    float zacc[16][4] = {};

    for (int hl = 0; hl < 4; hl++) {
        int head = head0 + hl;

        float c[4][4] = {};
#pragma unroll 4
        for (int ks = 0; ks < 16; ks++) {
            uint32_t kb2 = ks * 32;
            uint32_t ahi[4], alo[4];
            ldsm_x4(ahi, sbase + qoff + kb2);
            ldsm_x4(alo, sbase + TEB + qoff + kb2);
            uint32_t bh[4][2], bl[4][2];
#pragma unroll
            for (int ni = 0; ni < 4; ni++) {
                uint32_t ba = KB + koff + ni * (8 * TP * 2) + kb2;
                ldsm_x2(bh[ni], ba);
                ldsm_x2(bl[ni], ba + TEB);
            }
#pragma unroll
            for (int ni = 0; ni < 4; ni++) mma16816(c[ni], ahi, bh[ni]);
#pragma unroll
            for (int ni = 0; ni < 4; ni++) mma16816(c[ni], alo, bh[ni]);
#pragma unroll
            for (int ni = 0; ni < 4; ni++) mma16816(c[ni], ahi, bl[ni]);
        }

        float m0 = -1e30f, m1 = -1e30f;
#pragma unroll
        for (int ni = 0; ni < 4; ni++) {
            m0 = fmaxf(m0, fmaxf(c[ni][0], c[ni][1]));
            m1 = fmaxf(m1, fmaxf(c[ni][2], c[ni][3]));
        }
        m0 = fmaxf(m0, __shfl_xor_sync(0xffffffffu, m0, 1));
        m0 = fmaxf(m0, __shfl_xor_sync(0xffffffffu, m0, 2));
        m1 = fmaxf(m1, __shfl_xor_sync(0xffffffffu, m1, 1));
        m1 = fmaxf(m1, __shfl_xor_sync(0xffffffffu, m1, 2));
        if (tig == 0) {
            stmax[row0 * 2 + warpn] = m0;
            stmax[row1 * 2 + warpn] = m1;
        }
        __syncthreads();
        m0 = fmaxf(stmax[row0 * 2], stmax[row0 * 2 + 1]);
        m1 = fmaxf(stmax[row1 * 2], stmax[row1 * 2 + 1]);
        float s0 = 0.f, s1 = 0.f;
#pragma unroll
        for (int ni = 0; ni < 4; ni++) {
            c[ni][0] = __expf(c[ni][0] - m0);
            c[ni][1] = __expf(c[ni][1] - m0);
            c[ni][2] = __expf(c[ni][2] - m1);
            c[ni][3] = __expf(c[ni][3] - m1);
            s0 += c[ni][0] + c[ni][1];
            s1 += c[ni][2] + c[ni][3];
        }
        s0 += __shfl_xor_sync(0xffffffffu, s0, 1);
        s0 += __shfl_xor_sync(0xffffffffu, s0, 2);
        s1 += __shfl_xor_sync(0xffffffffu, s1, 1);
        s1 += __shfl_xor_sync(0xffffffffu, s1, 2);
        if (tig == 0) {
            stsum[row0 * 2 + warpn] = s0;
            stsum[row1 * 2 + warpn] = s1;
        }
        __syncthreads();
        float inv0 = 1.0f / (stsum[row0 * 2] + stsum[row0 * 2 + 1]);
        float inv1 = 1.0f / (stsum[row1 * 2] + stsum[row1 * 2 + 1]);
#pragma unroll
        for (int ni = 0; ni < 4; ni++) {
            int cn = warpn * 32 + ni * 8 + 2 * tig;
            bf16 h0, l0, h1, l1;
            bsplit(c[ni][0] * inv0, h0, l0); bsplit(c[ni][1] * inv0, h1, l1);
            *(__nv_bfloat162*)(Ph + row0 * PP + cn) = __nv_bfloat162(h0, h1);
            *(__nv_bfloat162*)(Pl + row0 * PP + cn) = __nv_bfloat162(l0, l1);
            bsplit(c[ni][2] * inv1, h0, l0); bsplit(c[ni][3] * inv1, h1, l1);
            *(__nv_bfloat162*)(Ph + row1 * PP + cn) = __nv_bfloat162(h0, h1);
            *(__nv_bfloat162*)(Pl + row1 * PP + cn) = __nv_bfloat162(l0, l1);
        }
        __syncthreads();

        if (hl < 3) {
            load_piece(0, (head + 1) * 256);
            asm volatile("cp.async.commit_group;\n");
        }

        const float* sop = g_so + head * 256;
#pragma unroll
        for (int ks = 0; ks < 4; ks++) {
            uint32_t kb2 = ks * 32;
            uint32_t ph[4], pl[4];
            ldsm_x4(ph, PB + poff + kb2);
            ldsm_x4(pl, PB + PPB + poff + kb2);
            uint32_t vrow = VB + voff + (uint32_t)ks * (16 * TP * 2);
#pragma unroll
            for (int ni = 0; ni < 16; ni++) {
                uint32_t va = vrow + (uint32_t)((warpn * 128 + ni * 8) * 2);
                uint32_t bh[2], bl[2];
                ldsm_x2t(bh, va);
                ldsm_x2t(bl, va + TEB);
                float ot[4] = {};
                mma16816(ot, ph, bh);
                mma16816(ot, pl, bh);
                mma16816(ot, ph, bl);
                float2 sv = *(const float2*)(sop + warpn * 128 + ni * 8 + 2 * tig);
                zacc[ni][0] += ot[0] * sv.x; zacc[ni][1] += ot[1] * sv.y;
                zacc[ni][2] += ot[2] * sv.x; zacc[ni][3] += ot[3] * sv.y;
            }
        }

        if (hl < 3) asm volatile("cp.async.wait_group 0;\n");
        __syncthreads();
    }

    float* gz = gridmode ? g_z1 : g_z2;
    size_t tok0 = base + (size_t)row0 * stride;
    size_t tok1 = base + (size_t)row1 * stride;
#pragma unroll
    for (int ni = 0; ni < 16; ni++) {
        int col = warpn * 128 + ni * 8 + 2 * tig;
        *(float2*)(gz + tok0 * DD + col) = make_float2(zacc[ni][0], zacc[ni][1]);
        *(float2*)(gz + tok1 * DD + col) = make_float2(zacc[ni][2], zacc[ni][3]);
    }
}

// ---------------- launch ----------------
extern "C" void kernel_launch(void* const* d_in, const int* in_sizes, int n_in,
                              void* d_out, int out_size) {
    const float* x    = (const float*)d_in[0];
    const float* ln1w = (const float*)d_in[1];
    const float* ln1b = (const float*)d_in[2];
    const float* qw   = (const float*)d_in[3];
    const float* kw   = (const float*)d_in[4];
    const float* vw   = (const float*)d_in[5];
    const float* ow   = (const float*)d_in[6];
    const float* ln2w = (const float*)d_in[7];
    const float* ln2b = (const float*)d_in[8];
    const float* w1   = (const float*)d_in[9];
    const float* b1   = (const float*)d_in[10];
    const float* w2   = (const float*)d_in[11];
    const float* b2   = (const float*)d_in[12];
    float* out = (float*)d_out;

    bf16 *p_asp, *p_wsp, *p_w1sp, *p_w2sp, *p_qkvsp;
    float *p_x2;
    cudaGetSymbolAddress((void**)&p_asp,   g_asp);
    cudaGetSymbolAddress((void**)&p_wsp,   g_wsp);
    cudaGetSymbolAddress((void**)&p_w1sp,  g_w1sp);
    cudaGetSymbolAddress((void**)&p_w2sp,  g_w2sp);
    cudaGetSymbolAddress((void**)&p_qkvsp, g_qkvsp);
    cudaGetSymbolAddress((void**)&p_x2,    g_x2);

    cudaFuncSetAttribute(attn_mma_kernel, cudaFuncAttributeMaxDynamicSharedMemorySize,
                         ATTN_SMEM_B);
    cudaFuncSetAttribute(qkv_gemm_kernel, cudaFuncAttributeMaxDynamicSharedMemorySize, GSMEM);
    cudaFuncSetAttribute(mlp_fused_kernel, cudaFuncAttributeMaxDynamicSharedMemorySize, MLP2SMEM);

    prep_all_kernel<<<3328, 256>>>(qw, kw, vw, w1, w2, ow, p_w1sp, p_w2sp);   // 1
    ln1_kernel<<<NTOK / 8, 256>>>(x, ln1w, ln1b);                             // 2
    qkv_gemm_kernel<<<dim3(QKVC / 128, NTOK / 128), 256, GSMEM>>>(            // 3
        p_asp, p_wsp, p_qkvsp);
    attn_mma_kernel<<<1024, 256, ATTN_SMEM_B>>>();                            // 4
    mlp_fused_kernel<<<NTOK / 128, 256, MLP2SMEM>>>(                          // 5
        x, ln2w, ln2b, p_w1sp, p_w2sp, b1, b2, p_x2, out);
}

// round 17
// speedup vs baseline: 1.7591x; 1.0118x over previous
#include <cuda_runtime.h>
#include <cuda_bf16.h>
#include <cstdint>
#include <cstddef>

typedef __nv_bfloat16 bf16;

// ---------------- problem constants ----------------
#define NTOK     32768
#define DD       256
#define QKVC     2560

// ---------------- static scratch ----------------
__device__ bf16 g_asp  [(size_t)NTOK * 512];
__device__ bf16 g_wsp  [(size_t)QKVC * 512];
__device__ bf16 g_w1sp [(size_t)DD * 512];
__device__ bf16 g_w2sp [(size_t)DD * 512];
__device__ bf16 g_qkvsp[(size_t)NTOK * 5120];
__device__ float g_z1  [(size_t)NTOK * DD];
__device__ float g_z2  [(size_t)NTOK * DD];
__device__ float g_so  [2048];
__device__ float g_x2  [(size_t)NTOK * DD];

// ---------------- helpers ----------------
__device__ __forceinline__ void bsplit(float v, bf16& h, bf16& l) {
    h = __float2bfloat16_rn(v);
    l = __float2bfloat16_rn(v - __bfloat162float(h));
}
__device__ __forceinline__ void cpasync16(uint32_t s, const void* g) {
    asm volatile("cp.async.cg.shared.global [%0], [%1], 16;\n" :: "r"(s), "l"(g));
}
__device__ __forceinline__ void mma16816(float* c, const uint32_t* a, const uint32_t* b) {
    asm volatile(
        "mma.sync.aligned.m16n8k16.row.col.f32.bf16.bf16.f32 "
        "{%0,%1,%2,%3},{%4,%5,%6,%7},{%8,%9},{%0,%1,%2,%3};\n"
        : "+f"(c[0]), "+f"(c[1]), "+f"(c[2]), "+f"(c[3])
        : "r"(a[0]), "r"(a[1]), "r"(a[2]), "r"(a[3]), "r"(b[0]), "r"(b[1]));
}
__device__ __forceinline__ void ldsm_x4(uint32_t* r, uint32_t a) {
    asm volatile("ldmatrix.sync.aligned.m8n8.x4.shared.b16 {%0,%1,%2,%3}, [%4];"
        : "=r"(r[0]), "=r"(r[1]), "=r"(r[2]), "=r"(r[3]) : "r"(a));
}
__device__ __forceinline__ void ldsm_x2(uint32_t* r, uint32_t a) {
    asm volatile("ldmatrix.sync.aligned.m8n8.x2.shared.b16 {%0,%1}, [%2];"
        : "=r"(r[0]), "=r"(r[1]) : "r"(a));
}
__device__ __forceinline__ void ldsm_x2t(uint32_t* r, uint32_t a) {
    asm volatile("ldmatrix.sync.aligned.m8n8.x2.trans.shared.b16 {%0,%1}, [%2];"
        : "=r"(r[0]), "=r"(r[1]) : "r"(a));
}
__device__ __forceinline__ void store_split8(bf16* rowp, int col, float4 v0, float4 v1) {
    bf16 h[8], l[8];
    bsplit(v0.x, h[0], l[0]); bsplit(v0.y, h[1], l[1]);
    bsplit(v0.z, h[2], l[2]); bsplit(v0.w, h[3], l[3]);
    bsplit(v1.x, h[4], l[4]); bsplit(v1.y, h[5], l[5]);
    bsplit(v1.z, h[6], l[6]); bsplit(v1.w, h[7], l[7]);
#pragma unroll
    for (int i = 0; i < 4; i++) {
        rowp[col + i]             = h[i];
        rowp[col + 128 + i]       = h[4 + i];
        rowp[256 + col + i]       = l[i];
        rowp[256 + col + 128 + i] = l[4 + i];
    }
}

// ---------------- merged prep: wqkv | w1 | w2 | so | LN1 ----------------
__global__ void prep_all_kernel(const float* __restrict__ q,
                                const float* __restrict__ k,
                                const float* __restrict__ v,
                                const float* __restrict__ w1,
                                const float* __restrict__ w2,
                                const float* __restrict__ o,
                                const float* __restrict__ x,
                                const float* __restrict__ ln1w,
                                const float* __restrict__ ln1b,
                                bf16* __restrict__ w1sp,
                                bf16* __restrict__ w2sp) {
    int bx = blockIdx.x;
    int tid = threadIdx.x;
    if (bx < 2560) {
        int idx = bx * 256 + tid;
        int d = idx & 255, j = idx >> 8;
        float val;
        if (j < 2048) { int h = j >> 8, kk = j & 255; val = q[((size_t)(h * 256 + d)) * 256 + kk]; }
        else if (j < 2304) val = k[(size_t)d * 256 + (j - 2048)];
        else               val = v[(size_t)d * 256 + (j - 2304)];
        bf16 h16, l16; bsplit(val, h16, l16);
        g_wsp[(size_t)j * 512 + d]       = h16;
        g_wsp[(size_t)j * 512 + 256 + d] = l16;
    } else if (bx < 3072) {
        int bb = bx - 2560;
        const float* src = (bb < 256) ? w1 : w2;
        bf16* dst = (bb < 256) ? w1sp : w2sp;
        int idx = (bb & 255) * 256 + tid;
        int d = idx & 255, j = idx >> 8;
        float val = src[(size_t)d * 256 + j];
        bf16 h16, l16; bsplit(val, h16, l16);
        dst[(size_t)j * 512 + d]       = h16;
        dst[(size_t)j * 512 + 256 + d] = l16;
    } else if (bx < 3328) {
        int bxx = bx - 3072;
        int row  = (bxx * 256 + tid) >> 5;
        int lane = tid & 31;
        const float* rp = o + (size_t)row * 256;
        float4 a = ((const float4*)rp)[lane];
        float4 b = ((const float4*)rp)[lane + 32];
        float s = a.x + a.y + a.z + a.w + b.x + b.y + b.z + b.w;
#pragma unroll
        for (int off = 16; off > 0; off >>= 1) s += __shfl_xor_sync(0xffffffffu, s, off);
        if (lane == 0) g_so[row] = s;
    } else {
        // LN1 + block permute -> split bf16
        int gwarp = ((bx - 3328) * 256 + tid) >> 5;
        int lane  = tid & 31;
        const float* row = x + (size_t)gwarp * DD;
        float4 v0 = ((const float4*)row)[lane];
        float4 v1 = ((const float4*)row)[lane + 32];
        float s  = v0.x + v0.y + v0.z + v0.w + v1.x + v1.y + v1.z + v1.w;
        float sq = v0.x*v0.x + v0.y*v0.y + v0.z*v0.z + v0.w*v0.w
                 + v1.x*v1.x + v1.y*v1.y + v1.z*v1.z + v1.w*v1.w;
#pragma unroll
        for (int off = 16; off > 0; off >>= 1) {
            s  += __shfl_xor_sync(0xffffffffu, s,  off);
            sq += __shfl_xor_sync(0xffffffffu, sq, off);
        }
        float mean = s * (1.0f / 256.0f);
        float var  = sq * (1.0f / 256.0f) - mean * mean;
        float rstd = rsqrtf(var + 1e-5f);

        int b = gwarp >> 12, pos = gwarp & 4095;
        int h = pos >> 6, w = pos & 63;
        int m = ((h & 7) << 3) | (w & 7);
        int n = ((h >> 3) << 3) | (w >> 3);
        size_t orow = ((size_t)b << 12) | (unsigned)((m << 6) | n);

        float4 g0 = ((const float4*)ln1w)[lane];
        float4 g1 = ((const float4*)ln1w)[lane + 32];
        float4 b0 = ((const float4*)ln1b)[lane];
        float4 b1 = ((const float4*)ln1b)[lane + 32];
        float4 o0, o1;
        o0.x = (v0.x - mean) * rstd * g0.x + b0.x;
        o0.y = (v0.y - mean) * rstd * g0.y + b0.y;
        o0.z = (v0.z - mean) * rstd * g0.z + b0.z;
        o0.w = (v0.w - mean) * rstd * g0.w + b0.w;
        o1.x = (v1.x - mean) * rstd * g1.x + b1.x;
        o1.y = (v1.y - mean) * rstd * g1.y + b1.y;
        o1.z = (v1.z - mean) * rstd * g1.z + b1.z;
        o1.w = (v1.w - mean) * rstd * g1.w + b1.w;
        store_split8(g_asp + orow * 512, lane * 4, o0, o1);
    }
}

// ================= QKV GEMM (R14-proven) =================
#define GP 40
#define MATB (128 * GP * 2)
#define STAGEB (4 * MATB)
#define GSMEM (2 * STAGEB)

__global__ __launch_bounds__(256, 2)
void qkv_gemm_kernel(const bf16* __restrict__ Asp,
                     const bf16* __restrict__ Bsp,
                     bf16* __restrict__ Csp) {
    extern __shared__ bf16 smem[];
    uint32_t sb = (uint32_t)__cvta_generic_to_shared(smem);

    int tid = threadIdx.x;
    int lane = tid & 31, warp = tid >> 5;
    int wm = warp & 1, wn = warp >> 1;
    int g = lane >> 2, tig = lane & 3;
    int lrow8 = lane & 7, l8 = (lane >> 3) & 1, l16 = (lane >> 4) & 1;
    int rowBase = blockIdx.y * 128;
    int colBase = blockIdx.x * 128;

    uint32_t aoff = (uint32_t)(((wm * 64 + lrow8 + 8 * l8) * GP + 8 * l16) * 2);
    uint32_t boff = (uint32_t)(((wn * 32 + lrow8) * GP + 8 * l8) * 2);

    float acc[4][4][4] = {};

    auto load_chunk = [&](int c, int st) {
        const bf16* Ag = Asp + (size_t)rowBase * 512 + c * 32;
        const bf16* Bg = Bsp + (size_t)colBase * 512 + c * 32;
        uint32_t base = sb + (uint32_t)st * STAGEB;
#pragma unroll
        for (int i = 0; i < 2; i++) {
            int f = tid + i * 256;
            int r = f >> 2, q = f & 3;
            uint32_t so = (uint32_t)(r * GP + q * 8) * 2;
            const bf16* ga = Ag + (size_t)r * 512 + q * 8;
            const bf16* gb = Bg + (size_t)r * 512 + q * 8;
            cpasync16(base + so,            ga);
            cpasync16(base + MATB + so,     ga + 256);
            cpasync16(base + 2 * MATB + so, gb);
            cpasync16(base + 3 * MATB + so, gb + 256);
        }
        asm volatile("cp.async.commit_group;\n");
    };

    load_chunk(0, 0);
    const int NCH = 8;
    for (int c = 0; c < NCH; c++) {
        if (c + 1 < NCH) {
            load_chunk(c + 1, (c + 1) & 1);
            asm volatile("cp.async.wait_group 1;\n");
        } else {
            asm volatile("cp.async.wait_group 0;\n");
        }
        __syncthreads();

        uint32_t stb = sb + (uint32_t)(c & 1) * STAGEB;
#pragma unroll
        for (int ks = 0; ks < 2; ks++) {
            uint32_t kb2 = ks * 32;
            uint32_t ahi[4][4], alo[4][4];
#pragma unroll
            for (int mi = 0; mi < 4; mi++) {
                uint32_t a = stb + aoff + mi * (16 * GP * 2) + kb2;
                ldsm_x4(ahi[mi], a);
                ldsm_x4(alo[mi], a + MATB);
            }
#pragma unroll
            for (int ni = 0; ni < 4; ni++) {
                uint32_t ba = stb + 2 * MATB + boff + ni * (8 * GP * 2) + kb2;
                uint32_t bh[2], bl[2];
                ldsm_x2(bh, ba);
                ldsm_x2(bl, ba + MATB);
#pragma unroll
                for (int mi = 0; mi < 4; mi++) mma16816(acc[mi][ni], ahi[mi], bh);
#pragma unroll
                for (int mi = 0; mi < 4; mi++) mma16816(acc[mi][ni], alo[mi], bh);
#pragma unroll
                for (int mi = 0; mi < 4; mi++) mma16816(acc[mi][ni], ahi[mi], bl);
            }
        }
        __syncthreads();
    }

#pragma unroll
    for (int mi = 0; mi < 4; mi++) {
        int r0 = rowBase + wm * 64 + mi * 16 + g;
        int r1 = r0 + 8;
#pragma unroll
        for (int ni = 0; ni < 4; ni++) {
            int col = colBase + wn * 32 + ni * 8 + tig * 2;
            bf16 h0, l0, h1, l1;
            bsplit(acc[mi][ni][0], h0, l0); bsplit(acc[mi][ni][1], h1, l1);
            *(__nv_bfloat162*)(Csp + (size_t)r0 * 5120 + col)        = __nv_bfloat162(h0, h1);
            *(__nv_bfloat162*)(Csp + (size_t)r0 * 5120 + 2560 + col) = __nv_bfloat162(l0, l1);
            bsplit(acc[mi][ni][2], h0, l0); bsplit(acc[mi][ni][3], h1, l1);
            *(__nv_bfloat162*)(Csp + (size_t)r1 * 5120 + col)        = __nv_bfloat162(h0, h1);
            *(__nv_bfloat162*)(Csp + (size_t)r1 * 5120 + 2560 + col) = __nv_bfloat162(l0, l1);
        }
    }
}

// ================= fused zred+LN2+MLP (R16-proven) =================
#define WGP 40
#define B_PL (256 * WGP * 2)
#define AP2 520
#define HP 264
#define HPLANE (128 * HP * 2)
#define STG0 (2 * HPLANE)
#define BSTG (2 * B_PL)
#define MLP2SMEM (STG0 + 2 * BSTG)

__global__ __launch_bounds__(256, 1)
void mlp_fused_kernel(const float* __restrict__ x,
                      const float* __restrict__ gamma,
                      const float* __restrict__ beta,
                      const bf16* __restrict__ w1sp,
                      const bf16* __restrict__ w2sp,
                      const float* __restrict__ b1,
                      const float* __restrict__ b2,
                      float* __restrict__ x2,
                      float* __restrict__ out) {
    extern __shared__ bf16 smem[];
    uint32_t sb = (uint32_t)__cvta_generic_to_shared(smem);

    int tid = threadIdx.x;
    int lane = tid & 31, warp = tid >> 5;
    int wm = warp & 1, wn = warp >> 1;
    int g = lane >> 2, tig = lane & 3;
    int lrow8 = lane & 7, l8 = (lane >> 3) & 1, l16 = (lane >> 4) & 1;
    int rowBase = blockIdx.x * 128;

    uint32_t aoff2 = (uint32_t)(((wm * 64 + lrow8 + 8 * l8) * AP2 + 8 * l16) * 2);
    uint32_t boff  = (uint32_t)(((wn * 64 + lrow8) * WGP + 8 * l8) * 2);
    uint32_t hoff  = (uint32_t)(((wm * 64 + lrow8 + 8 * l8) * HP + 8 * l16) * 2);

    auto loadB = [&](const bf16* Bg0, int c, int st) {
        const bf16* Bg = Bg0 + c * 32;
        uint32_t base = sb + STG0 + (uint32_t)st * BSTG;
#pragma unroll
        for (int i = 0; i < 4; i++) {
            int f = tid + i * 256;
            int r = f >> 2, q = f & 3;
            uint32_t so = (uint32_t)(r * WGP + q * 8) * 2;
            const bf16* gb = Bg + (size_t)r * 512 + q * 8;
            cpasync16(base + so,        gb);
            cpasync16(base + B_PL + so, gb + 256);
        }
        asm volatile("cp.async.commit_group;\n");
    };

    loadB(w1sp, 0, 0);

    // prologue: zred + LN2 -> smem A (forward map, R16-verified)
    {
        bf16* Asm = smem;
#pragma unroll 1
        for (int rr = 0; rr < 16; rr++) {
            int lr = warp * 16 + rr;
            int orow_ = rowBase + lr;
            int bb = orow_ >> 12, hh = (orow_ >> 6) & 63, ww = orow_ & 63;
            int mm = ((hh & 7) << 3) | (ww & 7);
            int nn = ((hh >> 3) << 3) | (ww >> 3);
            size_t gw = ((size_t)bb << 12) | (unsigned)((mm << 6) | nn);

            const float* z1p = g_z1 + gw * DD;
            const float* z2p = g_z2 + gw * DD;
            const float* xp  = x + (size_t)orow_ * DD;
            float4 a0 = ((const float4*)z1p)[lane];
            float4 a1 = ((const float4*)z1p)[lane + 32];
            float4 c0 = ((const float4*)z2p)[lane];
            float4 c1 = ((const float4*)z2p)[lane + 32];
            float4 x0 = ((const float4*)xp)[lane];
            float4 x1 = ((const float4*)xp)[lane + 32];
            float4 v0 = make_float4(x0.x + a0.x + c0.x, x0.y + a0.y + c0.y,
                                    x0.z + a0.z + c0.z, x0.w + a0.w + c0.w);
            float4 v1 = make_float4(x1.x + a1.x + c1.x, x1.y + a1.y + c1.y,
                                    x1.z + a1.z + c1.z, x1.w + a1.w + c1.w);

            ((float4*)(x2 + (size_t)orow_ * DD))[lane]      = v0;
            ((float4*)(x2 + (size_t)orow_ * DD))[lane + 32] = v1;

            float s  = v0.x + v0.y + v0.z + v0.w + v1.x + v1.y + v1.z + v1.w;
            float sq = v0.x*v0.x + v0.y*v0.y + v0.z*v0.z + v0.w*v0.w
                     + v1.x*v1.x + v1.y*v1.y + v1.z*v1.z + v1.w*v1.w;
#pragma unroll
            for (int o = 16; o > 0; o >>= 1) {
                s  += __shfl_xor_sync(0xffffffffu, s,  o);
                sq += __shfl_xor_sync(0xffffffffu, sq, o);
            }
            float mean = s * (1.0f / 256.0f);
            float var  = sq * (1.0f / 256.0f) - mean * mean;
            float rstd = rsqrtf(var + 1e-5f);

            float4 g0 = ((const float4*)gamma)[lane];
            float4 g1 = ((const float4*)gamma)[lane + 32];
            float4 bb0 = ((const float4*)beta)[lane];
            float4 bb1 = ((const float4*)beta)[lane + 32];
            float4 o0, o1;
            o0.x = (v0.x - mean) * rstd * g0.x + bb0.x;
            o0.y = (v0.y - mean) * rstd * g0.y + bb0.y;
            o0.z = (v0.z - mean) * rstd * g0.z + bb0.z;
            o0.w = (v0.w - mean) * rstd * g0.w + bb0.w;
            o1.x = (v1.x - mean) * rstd * g1.x + bb1.x;
            o1.y = (v1.y - mean) * rstd * g1.y + bb1.y;
            o1.z = (v1.z - mean) * rstd * g1.z + bb1.z;
            o1.w = (v1.w - mean) * rstd * g1.w + bb1.w;
            store_split8(Asm + (size_t)lr * AP2, lane * 4, o0, o1);
        }
    }
    __syncthreads();

    float acc[4][8][4] = {};

    for (int c = 0; c < 8; c++) {
        if (c + 1 < 8) {
            loadB(w1sp, c + 1, (c + 1) & 1);
            asm volatile("cp.async.wait_group 1;\n");
        } else {
            asm volatile("cp.async.wait_group 0;\n");
        }
        __syncthreads();
        uint32_t stg = sb + STG0 + (uint32_t)(c & 1) * BSTG;
#pragma unroll
        for (int ks = 0; ks < 2; ks++) {
            uint32_t kbyte = (uint32_t)((c * 32 + ks * 16) * 2);
            uint32_t kb2 = ks * 32;
            uint32_t ahi[4][4], alo[4][4];
#pragma unroll
            for (int mi = 0; mi < 4; mi++) {
                uint32_t a = sb + aoff2 + mi * (16 * AP2 * 2) + kbyte;
                ldsm_x4(ahi[mi], a);
                ldsm_x4(alo[mi], a + 512);
            }
#pragma unroll
            for (int ni = 0; ni < 8; ni++) {
                uint32_t ba = stg + boff + ni * (8 * WGP * 2) + kb2;
                uint32_t bh[2], bl[2];
                ldsm_x2(bh, ba);
                ldsm_x2(bl, ba + B_PL);
#pragma unroll
                for (int mi = 0; mi < 4; mi++) mma16816(acc[mi][ni], ahi[mi], bh);
#pragma unroll
                for (int mi = 0; mi < 4; mi++) mma16816(acc[mi][ni], alo[mi], bh);
#pragma unroll
                for (int mi = 0; mi < 4; mi++) mma16816(acc[mi][ni], ahi[mi], bl);
            }
        }
        __syncthreads();
    }

    loadB(w2sp, 0, 0);

    bf16* hhi = smem;
    bf16* hlo = smem + 128 * HP;
#pragma unroll
    for (int mi = 0; mi < 4; mi++) {
        int r0 = wm * 64 + mi * 16 + g;
        int r1 = r0 + 8;
#pragma unroll
        for (int ni = 0; ni < 8; ni++) {
            int col = wn * 64 + ni * 8 + tig * 2;
            float2 bv = *(const float2*)(b1 + col);
            float v0 = fmaxf(acc[mi][ni][0] + bv.x, 0.f);
            float v1 = fmaxf(acc[mi][ni][1] + bv.y, 0.f);
            float v2 = fmaxf(acc[mi][ni][2] + bv.x, 0.f);
            float v3 = fmaxf(acc[mi][ni][3] + bv.y, 0.f);
            bf16 h0, l0, h1, l1;
            bsplit(v0, h0, l0); bsplit(v1, h1, l1);
            *(__nv_bfloat162*)(hhi + r0 * HP + col) = __nv_bfloat162(h0, h1);
            *(__nv_bfloat162*)(hlo + r0 * HP + col) = __nv_bfloat162(l0, l1);
            bsplit(v2, h0, l0); bsplit(v3, h1, l1);
            *(__nv_bfloat162*)(hhi + r1 * HP + col) = __nv_bfloat162(h0, h1);
            *(__nv_bfloat162*)(hlo + r1 * HP + col) = __nv_bfloat162(l0, l1);
            acc[mi][ni][0] = 0.f; acc[mi][ni][1] = 0.f;
            acc[mi][ni][2] = 0.f; acc[mi][ni][3] = 0.f;
        }
    }
    __syncthreads();

    for (int c = 0; c < 8; c++) {
        if (c + 1 < 8) {
            loadB(w2sp, c + 1, (c + 1) & 1);
            asm volatile("cp.async.wait_group 1;\n");
        } else {
            asm volatile("cp.async.wait_group 0;\n");
        }
        __syncthreads();
        uint32_t stg = sb + STG0 + (uint32_t)(c & 1) * BSTG;
#pragma unroll
        for (int ks = 0; ks < 2; ks++) {
            uint32_t kbyte = (uint32_t)((c * 32 + ks * 16) * 2);
            uint32_t kb2 = ks * 32;
            uint32_t ahi[4][4], alo[4][4];
#pragma unroll
            for (int mi = 0; mi < 4; mi++) {
                uint32_t a = sb + hoff + mi * (16 * HP * 2) + kbyte;
                ldsm_x4(ahi[mi], a);
                ldsm_x4(alo[mi], a + HPLANE);
            }
#pragma unroll
            for (int ni = 0; ni < 8; ni++) {
                uint32_t ba = stg + boff + ni * (8 * WGP * 2) + kb2;
                uint32_t bh[2], bl[2];
                ldsm_x2(bh, ba);
                ldsm_x2(bl, ba + B_PL);
#pragma unroll
                for (int mi = 0; mi < 4; mi++) mma16816(acc[mi][ni], ahi[mi], bh);
#pragma unroll
                for (int mi = 0; mi < 4; mi++) mma16816(acc[mi][ni], alo[mi], bh);
#pragma unroll
                for (int mi = 0; mi < 4; mi++) mma16816(acc[mi][ni], ahi[mi], bl);
            }
        }
        __syncthreads();
    }

#pragma unroll
    for (int mi = 0; mi < 4; mi++) {
        int r0 = rowBase + wm * 64 + mi * 16 + g;
        int r1 = r0 + 8;
#pragma unroll
        for (int ni = 0; ni < 8; ni++) {
            int col = wn * 64 + ni * 8 + tig * 2;
            float2 bv = *(const float2*)(b2 + col);
            float2 e0 = *(const float2*)(x2 + (size_t)r0 * DD + col);
            float2 e1 = *(const float2*)(x2 + (size_t)r1 * DD + col);
            float2 v0 = make_float2(acc[mi][ni][0] + bv.x + e0.x,
                                    acc[mi][ni][1] + bv.y + e0.y);
            float2 v1 = make_float2(acc[mi][ni][2] + bv.x + e1.x,
                                    acc[mi][ni][3] + bv.y + e1.y);
            *(float2*)(out + (size_t)r0 * DD + col) = v0;
            *(float2*)(out + (size_t)r1 * DD + col) = v1;
        }
    }
}

// ================= attention: 512 threads, 16 warps (4x4) =================
#define TP 264
#define PP 72
#define TILE_E (64 * TP)
#define TEB (TILE_E * 2)
#define PPB (64 * PP * 2)
#define ATTN_SMEM_B (6 * TEB + 2 * PPB + 2048)

__global__ __launch_bounds__(512)
void attn_mma_kernel() {
    extern __shared__ bf16 asm_[];
    bf16* Ph = asm_ + 6 * TILE_E;
    bf16* Pl = Ph + 64 * PP;
    float* stmax = (float*)(Pl + 64 * PP);   // [64][4]
    float* stsum = stmax + 256;              // [64][4]
    uint32_t sbase = (uint32_t)__cvta_generic_to_shared(asm_);

    int tid = threadIdx.x;
    int lane = tid & 31, warp = tid >> 5;
    int g = lane >> 2, tig = lane & 3;
    int lrow8 = lane & 7, l8 = (lane >> 3) & 1, l16 = (lane >> 4) & 1;

    int u = blockIdx.x;
    bool gridmode = (u < 512);
    int b, fix;
    if (gridmode) { b = u >> 6; fix = u & 63; }
    else          { int u2 = u - 512; b = u2 >> 6; fix = u2 & 63; }
    size_t base; int stride;
    if (gridmode) { base = (size_t)b * 4096 + fix; stride = 64; }
    else          { base = (size_t)b * 4096 + (size_t)fix * 64; stride = 1; }
    int head0 = gridmode ? 0 : 4;

    auto load_piece = [&](int planeIdx, int colOff) {
        uint32_t sh = sbase + (uint32_t)planeIdx * TEB;
#pragma unroll
        for (int i = 0; i < 4; i++) {
            int f = i * 512 + tid;
            int r = f >> 5, q = f & 31;
            size_t token = base + (size_t)r * stride;
            const bf16* ga = g_qkvsp + token * 5120 + colOff + q * 8;
            uint32_t so = (uint32_t)(r * TP + q * 8) * 2;
            cpasync16(sh + so, ga);
            cpasync16(sh + TEB + so, ga + 2560);
        }
    };

    load_piece(2, 2048);
    load_piece(4, 2304);
    load_piece(0, head0 * 256);
    asm volatile("cp.async.commit_group;\n");
    asm volatile("cp.async.wait_group 0;\n");
    __syncthreads();

    int warpm = warp >> 2, warpn = warp & 3;        // 4 x 4 warps
    int row0 = warpm * 16 + g, row1 = row0 + 8;

    uint32_t qoff = (uint32_t)(((warpm * 16 + lrow8 + 8 * l8) * TP + 8 * l16) * 2);
    uint32_t koff = (uint32_t)(((warpn * 16 + lrow8) * TP + 8 * l8) * 2);
    uint32_t poff = (uint32_t)(((warpm * 16 + lrow8 + 8 * l8) * PP + 8 * l16) * 2);
    uint32_t voff = (uint32_t)(((lrow8 + 8 * l8) * TP) * 2);
    uint32_t PB = sbase + 6 * TEB;
    uint32_t KB = sbase + 2 * TEB;
    uint32_t VB = sbase + 4 * TEB;

    float zacc[8][4] = {};

    for (int hl = 0; hl < 4; hl++) {
        int head = head0 + hl;

        // ---------- S = Q K^T  (16x16 per warp) ----------
        float c[2][4] = {};
#pragma unroll 4
        for (int ks = 0; ks < 16; ks++) {
            uint32_t kb2 = ks * 32;
            uint32_t ahi[4], alo[4];
            ldsm_x4(ahi, sbase + qoff + kb2);
            ldsm_x4(alo, sbase + TEB + qoff + kb2);
            uint32_t bh[2][2], bl[2][2];
#pragma unroll
            for (int ni = 0; ni < 2; ni++) {
                uint32_t ba = KB + koff + ni * (8 * TP * 2) + kb2;
                ldsm_x2(bh[ni], ba);
                ldsm_x2(bl[ni], ba + TEB);
            }
#pragma unroll
            for (int ni = 0; ni < 2; ni++) mma16816(c[ni], ahi, bh[ni]);
#pragma unroll
            for (int ni = 0; ni < 2; ni++) mma16816(c[ni], alo, bh[ni]);
#pragma unroll
            for (int ni = 0; ni < 2; ni++) mma16816(c[ni], ahi, bl[ni]);
        }

        // ---------- softmax (4 partials per row) ----------
        float m0 = -1e30f, m1 = -1e30f;
#pragma unroll
        for (int ni = 0; ni < 2; ni++) {
            m0 = fmaxf(m0, fmaxf(c[ni][0], c[ni][1]));
            m1 = fmaxf(m1, fmaxf(c[ni][2], c[ni][3]));
        }
        m0 = fmaxf(m0, __shfl_xor_sync(0xffffffffu, m0, 1));
        m0 = fmaxf(m0, __shfl_xor_sync(0xffffffffu, m0, 2));
        m1 = fmaxf(m1, __shfl_xor_sync(0xffffffffu, m1, 1));
        m1 = fmaxf(m1, __shfl_xor_sync(0xffffffffu, m1, 2));
        if (tig == 0) {
            stmax[row0 * 4 + warpn] = m0;
            stmax[row1 * 4 + warpn] = m1;
        }
        __syncthreads();
        m0 = fmaxf(fmaxf(stmax[row0 * 4], stmax[row0 * 4 + 1]),
                   fmaxf(stmax[row0 * 4 + 2], stmax[row0 * 4 + 3]));
        m1 = fmaxf(fmaxf(stmax[row1 * 4], stmax[row1 * 4 + 1]),
                   fmaxf(stmax[row1 * 4 + 2], stmax[row1 * 4 + 3]));
        float s0 = 0.f, s1 = 0.f;
#pragma unroll
        for (int ni = 0; ni < 2; ni++) {
            c[ni][0] = __expf(c[ni][0] - m0);
            c[ni][1] = __expf(c[ni][1] - m0);
            c[ni][2] = __expf(c[ni][2] - m1);
            c[ni][3] = __expf(c[ni][3] - m1);
            s0 += c[ni][0] + c[ni][1];
            s1 += c[ni][2] + c[ni][3];
        }
        s0 += __shfl_xor_sync(0xffffffffu, s0, 1);
        s0 += __shfl_xor_sync(0xffffffffu, s0, 2);
        s1 += __shfl_xor_sync(0xffffffffu, s1, 1);
        s1 += __shfl_xor_sync(0xffffffffu, s1, 2);
        if (tig == 0) {
            stsum[row0 * 4 + warpn] = s0;
            stsum[row1 * 4 + warpn] = s1;
        }
        __syncthreads();
        float inv0 = 1.0f / (stsum[row0 * 4] + stsum[row0 * 4 + 1]
                           + stsum[row0 * 4 + 2] + stsum[row0 * 4 + 3]);
        float inv1 = 1.0f / (stsum[row1 * 4] + stsum[row1 * 4 + 1]
                           + stsum[row1 * 4 + 2] + stsum[row1 * 4 + 3]);
#pragma unroll
        for (int ni = 0; ni < 2; ni++) {
            int cn = warpn * 16 + ni * 8 + 2 * tig;
            bf16 h0, l0, h1, l1;
            bsplit(c[ni][0] * inv0, h0, l0); bsplit(c[ni][1] * inv0, h1, l1);
            *(__nv_bfloat162*)(Ph + row0 * PP + cn) = __nv_bfloat162(h0, h1);
            *(__nv_bfloat162*)(Pl + row0 * PP + cn) = __nv_bfloat162(l0, l1);
            bsplit(c[ni][2] * inv1, h0, l0); bsplit(c[ni][3] * inv1, h1, l1);
            *(__nv_bfloat162*)(Ph + row1 * PP + cn) = __nv_bfloat162(h0, h1);
            *(__nv_bfloat162*)(Pl + row1 * PP + cn) = __nv_bfloat162(l0, l1);
        }
        __syncthreads();

        if (hl < 3) {
            load_piece(0, (head + 1) * 256);
            asm volatile("cp.async.commit_group;\n");
        }

        // ---------- O = P V (16x64 per warp), so-scaled ----------
        const float* sop = g_so + head * 256;
#pragma unroll
        for (int ks = 0; ks < 4; ks++) {
            uint32_t kb2 = ks * 32;
            uint32_t ph[4], pl[4];
            ldsm_x4(ph, PB + poff + kb2);
            ldsm_x4(pl, PB + PPB + poff + kb2);
            uint32_t vrow = VB + voff + (uint32_t)ks * (16 * TP * 2);
#pragma unroll
            for (int ni = 0; ni < 8; ni++) {
                uint32_t va = vrow + (uint32_t)((warpn * 64 + ni * 8) * 2);
                uint32_t bh[2], bl[2];
                ldsm_x2t(bh, va);
                ldsm_x2t(bl, va + TEB);
                float ot[4] = {};
                mma16816(ot, ph, bh);
                mma16816(ot, pl, bh);
                mma16816(ot, ph, bl);
                float2 sv = *(const float2*)(sop + warpn * 64 + ni * 8 + 2 * tig);
                zacc[ni][0] += ot[0] * sv.x; zacc[ni][1] += ot[1] * sv.y;
                zacc[ni][2] += ot[2] * sv.x; zacc[ni][3] += ot[3] * sv.y;
            }
        }

        if (hl < 3) asm volatile("cp.async.wait_group 0;\n");
        __syncthreads();
    }

    float* gz = gridmode ? g_z1 : g_z2;
    size_t tok0 = base + (size_t)row0 * stride;
    size_t tok1 = base + (size_t)row1 * stride;
#pragma unroll
    for (int ni = 0; ni < 8; ni++) {
        int col = warpn * 64 + ni * 8 + 2 * tig;
        *(float2*)(gz + tok0 * DD + col) = make_float2(zacc[ni][0], zacc[ni][1]);
        *(float2*)(gz + tok1 * DD + col) = make_float2(zacc[ni][2], zacc[ni][3]);
    }
}

// ---------------- launch ----------------
extern "C" void kernel_launch(void* const* d_in, const int* in_sizes, int n_in,
                              void* d_out, int out_size) {
    const float* x    = (const float*)d_in[0];
    const float* ln1w = (const float*)d_in[1];
    const float* ln1b = (const float*)d_in[2];
    const float* qw   = (const float*)d_in[3];
    const float* kw   = (const float*)d_in[4];
    const float* vw   = (const float*)d_in[5];
    const float* ow   = (const float*)d_in[6];
    const float* ln2w = (const float*)d_in[7];
    const float* ln2b = (const float*)d_in[8];
    const float* w1   = (const float*)d_in[9];
    const float* b1   = (const float*)d_in[10];
    const float* w2   = (const float*)d_in[11];
    const float* b2   = (const float*)d_in[12];
    float* out = (float*)d_out;

    bf16 *p_asp, *p_wsp, *p_w1sp, *p_w2sp, *p_qkvsp;
    float *p_x2;
    cudaGetSymbolAddress((void**)&p_asp,   g_asp);
    cudaGetSymbolAddress((void**)&p_wsp,   g_wsp);
    cudaGetSymbolAddress((void**)&p_w1sp,  g_w1sp);
    cudaGetSymbolAddress((void**)&p_w2sp,  g_w2sp);
    cudaGetSymbolAddress((void**)&p_qkvsp, g_qkvsp);
    cudaGetSymbolAddress((void**)&p_x2,    g_x2);

    cudaFuncSetAttribute(attn_mma_kernel, cudaFuncAttributeMaxDynamicSharedMemorySize,
                         ATTN_SMEM_B);
    cudaFuncSetAttribute(qkv_gemm_kernel, cudaFuncAttributeMaxDynamicSharedMemorySize, GSMEM);
    cudaFuncSetAttribute(mlp_fused_kernel, cudaFuncAttributeMaxDynamicSharedMemorySize, MLP2SMEM);

    // 1: merged prep (wqkv/w1/w2/so) + LN1 (blocks 3328..7423)
    prep_all_kernel<<<3328 + 4096, 256>>>(qw, kw, vw, w1, w2, ow,
                                          x, ln1w, ln1b, p_w1sp, p_w2sp);
    // 2: QKV projection
    qkv_gemm_kernel<<<dim3(QKVC / 128, NTOK / 128), 256, GSMEM>>>(
        p_asp, p_wsp, p_qkvsp);
    // 3: attention (512 threads, 16 warps)
    attn_mma_kernel<<<1024, 512, ATTN_SMEM_B>>>();
    // 4: fused zred+LN2+MLP
    mlp_fused_kernel<<<NTOK / 128, 256, MLP2SMEM>>>(
        x, ln2w, ln2b, p_w1sp, p_w2sp, b1, b2, p_x2, out);
}